// round 2
// baseline (speedup 1.0000x reference)
#include <cuda_runtime.h>
#include <math.h>

#define NNODE 20000
#define EL 80000
#define EB 60000
#define EG 400000
#define SCALE 0.17677669529663687f   // 1/sqrt(32)

// ---------------- scratch (static device globals: allowed) ----------------
__device__ float d_q[NNODE * 512];
__device__ float d_k[NNODE * 512];
__device__ float d_v[NNODE * 512];
__device__ float d_kg[NNODE * 256];
__device__ float d_abvb[EB * 512];
__device__ float d_absum[EB * 8];
__device__ float d_dsum[65 * 8];
__device__ float d_sloc[EL * 8];
__device__ float d_sg[EG * 8];
__device__ float d_mloc[NNODE * 8];
__device__ float d_dloc[NNODE * 8];
__device__ float d_mg[NNODE * 8];
__device__ float d_dg[NNODE * 8];
__device__ float d_cat[NNODE * 512];    // [local_out | global_out] numerators -> normalized
__device__ float d_cat2[EB * 512];      // [f_bond | out[src]]

// ---------------- helpers ----------------
__device__ __forceinline__ void atomicMaxF(float* a, float v) {
    if (v >= 0.f) atomicMax((int*)a, __float_as_int(v));
    else          atomicMin((unsigned int*)a, __float_as_uint(v));
}

__device__ __forceinline__ void redAdd4(float* p, float x, float y, float z, float w) {
    asm volatile("red.global.add.v4.f32 [%0], {%1,%2,%3,%4};"
                 :: "l"(p), "f"(x), "f"(y), "f"(z), "f"(w) : "memory");
}

// ---------------- SGEMM: C[M,N] = A[M,K] @ B[K,N] + bias[N] ----------------
// 128x128 tile, BK=8, 256 threads, 8x8 per thread. N,K multiples of 128/8; M guarded.
__global__ void __launch_bounds__(256) sgemm128(const float* __restrict__ A,
                                                const float* __restrict__ B,
                                                const float* __restrict__ bias,
                                                float* __restrict__ C,
                                                int M, int K, int N) {
    __shared__ float As[8][128];
    __shared__ float Bs[8][128];
    const int tid = threadIdx.x;
    const int bm = blockIdx.y * 128;
    const int bn = blockIdx.x * 128;
    const int rowA = tid >> 1, colA = (tid & 1) * 4;
    const int rowB = tid >> 5, colB = (tid & 31) * 4;
    const int ty = (tid >> 4) * 8, tx = (tid & 15) * 8;
    float acc[8][8];
#pragma unroll
    for (int i = 0; i < 8; i++)
#pragma unroll
        for (int j = 0; j < 8; j++) acc[i][j] = 0.f;

    const int gRowA = bm + rowA;
    const float* Aptr = A + (size_t)gRowA * K + colA;
    const float* Bptr = B + (size_t)rowB * N + bn + colB;

    for (int kt = 0; kt < K; kt += 8) {
        float4 av = make_float4(0.f, 0.f, 0.f, 0.f);
        if (gRowA < M) av = *(const float4*)(Aptr + kt);
        As[colA + 0][rowA] = av.x;
        As[colA + 1][rowA] = av.y;
        As[colA + 2][rowA] = av.z;
        As[colA + 3][rowA] = av.w;
        float4 bv = *(const float4*)(Bptr + (size_t)kt * N);
        *(float4*)&Bs[rowB][colB] = bv;
        __syncthreads();
#pragma unroll
        for (int k = 0; k < 8; k++) {
            float ra[8], rb[8];
#pragma unroll
            for (int i = 0; i < 8; i++) ra[i] = As[k][ty + i];
#pragma unroll
            for (int j = 0; j < 8; j++) rb[j] = Bs[k][tx + j];
#pragma unroll
            for (int i = 0; i < 8; i++)
#pragma unroll
                for (int j = 0; j < 8; j++) acc[i][j] += ra[i] * rb[j];
        }
        __syncthreads();
    }

#pragma unroll
    for (int i = 0; i < 8; i++) {
        int r = bm + ty + i;
        if (r < M) {
#pragma unroll
            for (int j = 0; j < 8; j += 4) {
                float4 o;
                o.x = acc[i][j + 0] + bias[bn + tx + j + 0];
                o.y = acc[i][j + 1] + bias[bn + tx + j + 1];
                o.z = acc[i][j + 2] + bias[bn + tx + j + 2];
                o.w = acc[i][j + 3] + bias[bn + tx + j + 3];
                *(float4*)&C[(size_t)r * N + bn + tx + j] = o;
            }
        }
    }
}

// ---------------- small kernels ----------------
__global__ void init_kernel() {
    int t = blockIdx.x * blockDim.x + threadIdx.x;
    if (t < NNODE * 512) d_cat[t] = 0.f;
    if (t < NNODE * 8) {
        d_dloc[t] = 0.f;
        d_dg[t] = 0.f;
        d_mloc[t] = __int_as_float(0xff800000);
        d_mg[t] = __int_as_float(0xff800000);
    }
}

__global__ void kg_kernel(const int* __restrict__ deg, const float* __restrict__ deg_emb) {
    int t = blockIdx.x * blockDim.x + threadIdx.x;
    if (t >= NNODE * 256) return;
    int n = t >> 8, c = t & 255;
    d_kg[t] = d_k[(size_t)n * 512 + 256 + c] + deg_emb[(size_t)deg[n] * 256 + c];
}

// per-edge per-head sum of attention_bond (first 256 cols of abvb)
__global__ void absum_kernel() {
    int e = blockIdx.x * (blockDim.x >> 5) + (threadIdx.x >> 5);
    if (e >= EB) return;
    int lane = threadIdx.x & 31;
    const float4* p = (const float4*)(d_abvb + (size_t)e * 512) + lane * 2;
    float4 a = p[0], b = p[1];
    float s = a.x + a.y + a.z + a.w + b.x + b.y + b.z + b.w;
    s += __shfl_xor_sync(0xffffffffu, s, 1);
    s += __shfl_xor_sync(0xffffffffu, s, 2);
    if ((lane & 3) == 0) d_absum[e * 8 + (lane >> 2)] = s;
}

__global__ void dsum_kernel(const float* __restrict__ dist_emb) {
    int t = blockIdx.x * blockDim.x + threadIdx.x;
    if (t >= 65 * 8) return;
    int r = t >> 3, h = t & 7;
    const float* p = dist_emb + (size_t)r * 256 + h * 32;
    float s = 0.f;
#pragma unroll
    for (int d = 0; d < 32; d++) s += p[d];
    d_dsum[t] = s;
}

// local scores: warp per edge (lane covers 8 consecutive cols; head = lane/4)
__global__ void lscore_kernel(const int* __restrict__ src_arr, const int* __restrict__ dst_arr) {
    int e = blockIdx.x * (blockDim.x >> 5) + (threadIdx.x >> 5);
    if (e >= EL) return;
    int lane = threadIdx.x & 31;
    int src = src_arr[e], dst = dst_arr[e];
    const float4* qp = (const float4*)(d_q + (size_t)dst * 512) + lane * 2;
    const float4* kp = (const float4*)(d_k + (size_t)src * 512) + lane * 2;
    float4 a0 = qp[0], a1 = qp[1], b0 = kp[0], b1 = kp[1];
    float s = a0.x * b0.x + a0.y * b0.y + a0.z * b0.z + a0.w * b0.w
            + a1.x * b1.x + a1.y * b1.y + a1.z * b1.z + a1.w * b1.w;
    s += __shfl_xor_sync(0xffffffffu, s, 1);
    s += __shfl_xor_sync(0xffffffffu, s, 2);
    if ((lane & 3) == 0) {
        int h = lane >> 2;
        if (e < EB) s += d_absum[e * 8 + h];
        s *= SCALE;
        d_sloc[e * 8 + h] = s;
        atomicMaxF(&d_mloc[dst * 8 + h], s);
    }
}

// global scores (base, no bond term yet)
__global__ void gscore_kernel(const int* __restrict__ qi, const int* __restrict__ ki,
                              const int* __restrict__ dist) {
    int e = blockIdx.x * (blockDim.x >> 5) + (threadIdx.x >> 5);
    if (e >= EG) return;
    int lane = threadIdx.x & 31;
    int a = qi[e], b = ki[e], dd = dist[e];
    const float4* qp = (const float4*)(d_q + (size_t)a * 512 + 256) + lane * 2;
    const float4* kp = (const float4*)(d_kg + (size_t)b * 256) + lane * 2;
    float4 a0 = qp[0], a1 = qp[1], b0 = kp[0], b1 = kp[1];
    float s = a0.x * b0.x + a0.y * b0.y + a0.z * b0.z + a0.w * b0.w
            + a1.x * b1.x + a1.y * b1.y + a1.z * b1.z + a1.w * b1.w;
    s += __shfl_xor_sync(0xffffffffu, s, 1);
    s += __shfl_xor_sync(0xffffffffu, s, 2);
    if ((lane & 3) == 0) {
        int h = lane >> 2;
        d_sg[(size_t)e * 8 + h] = (s + d_dsum[dd * 8 + h]) * SCALE;
    }
}

// scatter bond contribution into global scores via attention_bond_idx
__global__ void gbond_kernel(const int* __restrict__ abi) {
    int t = blockIdx.x * blockDim.x + threadIdx.x;
    if (t >= EB * 8) return;
    int j = t >> 3, h = t & 7;
    int e = abi[j];
    d_sg[(size_t)e * 8 + h] += d_absum[t] * SCALE;
}

__global__ void gmax_kernel(const int* __restrict__ qi) {
    int t = blockIdx.x * blockDim.x + threadIdx.x;
    if (t >= EG * 8) return;
    int e = t >> 3, h = t & 7;
    atomicMaxF(&d_mg[(size_t)qi[e] * 8 + h], d_sg[t]);
}

// local accumulate: unnormalized numerator + denominator
__global__ void laccum_kernel(const int* __restrict__ src_arr, const int* __restrict__ dst_arr) {
    int e = blockIdx.x * (blockDim.x >> 5) + (threadIdx.x >> 5);
    if (e >= EL) return;
    int lane = threadIdx.x & 31;
    int h = lane >> 2;
    int src = src_arr[e], dst = dst_arr[e];
    float w = __expf(d_sloc[e * 8 + h] - d_mloc[dst * 8 + h]);
    if ((lane & 3) == 0) atomicAdd(&d_dloc[dst * 8 + h], w);
    const float4* vp = (const float4*)(d_v + (size_t)src * 512) + lane * 2;
    float4 v0 = vp[0], v1 = vp[1];
    if (e < EB) {
        const float4* bp = (const float4*)(d_abvb + (size_t)e * 512 + 256) + lane * 2;
        float4 c0 = bp[0], c1 = bp[1];
        v0.x += c0.x; v0.y += c0.y; v0.z += c0.z; v0.w += c0.w;
        v1.x += c1.x; v1.y += c1.y; v1.z += c1.z; v1.w += c1.w;
    }
    float* outp = d_cat + (size_t)dst * 512 + lane * 8;
    redAdd4(outp,     w * v0.x, w * v0.y, w * v0.z, w * v0.w);
    redAdd4(outp + 4, w * v1.x, w * v1.y, w * v1.z, w * v1.w);
}

// global accumulate
__global__ void gaccum_kernel(const int* __restrict__ qi, const int* __restrict__ ki) {
    int e = blockIdx.x * (blockDim.x >> 5) + (threadIdx.x >> 5);
    if (e >= EG) return;
    int lane = threadIdx.x & 31;
    int h = lane >> 2;
    int a = qi[e], b = ki[e];
    float w = __expf(d_sg[(size_t)e * 8 + h] - d_mg[(size_t)a * 8 + h]);
    if ((lane & 3) == 0) atomicAdd(&d_dg[(size_t)a * 8 + h], w);
    const float4* vp = (const float4*)(d_v + (size_t)b * 512 + 256) + lane * 2;
    float4 v0 = vp[0], v1 = vp[1];
    float* outp = d_cat + (size_t)a * 512 + 256 + lane * 8;
    redAdd4(outp,     w * v0.x, w * v0.y, w * v0.z, w * v0.w);
    redAdd4(outp + 4, w * v1.x, w * v1.y, w * v1.z, w * v1.w);
}

__global__ void norm_kernel() {
    int t = blockIdx.x * blockDim.x + threadIdx.x;
    if (t >= NNODE * 512) return;
    int n = t >> 9, c = t & 511;
    float d = (c < 256) ? d_dloc[n * 8 + (c >> 5)] : d_dg[n * 8 + ((c - 256) >> 5)];
    float num = d_cat[t];
    d_cat[t] = (d > 0.f) ? num / d : 0.f;
}

__global__ void cat2_kernel(const float* __restrict__ f_bond, const int* __restrict__ src_arr,
                            const float* __restrict__ outp) {
    int t = blockIdx.x * blockDim.x + threadIdx.x;
    if (t >= EB * 512) return;
    int e = t >> 9, c = t & 511;
    d_cat2[t] = (c < 256) ? f_bond[(size_t)e * 256 + c]
                          : outp[(size_t)src_arr[e] * 256 + (c - 256)];
}

// ---------------- launch ----------------
extern "C" void kernel_launch(void* const* d_in, const int* in_sizes, int n_in,
                              void* d_out, int out_size) {
    const float* f_node      = (const float*)d_in[0];
    const float* f_bond      = (const float*)d_in[1];
    const int*   deg         = (const int*)d_in[2];
    const int*   dist        = (const int*)d_in[3];
    const int*   bond_idx    = (const int*)d_in[4];
    const int*   qidx        = (const int*)d_in[5];
    const int*   kidx        = (const int*)d_in[6];
    const int*   abi         = (const int*)d_in[7];
    const float* deg_emb     = (const float*)d_in[8];
    const float* dist_emb    = (const float*)d_in[9];
    const float* Wq_w        = (const float*)d_in[10];
    const float* Wq_b        = (const float*)d_in[11];
    const float* Wk_w        = (const float*)d_in[12];
    const float* Wk_b        = (const float*)d_in[13];
    const float* Wv_w        = (const float*)d_in[14];
    const float* Wv_b        = (const float*)d_in[15];
    const float* out_w       = (const float*)d_in[16];
    const float* out_b       = (const float*)d_in[17];
    const float* bond_emb_w  = (const float*)d_in[18];
    const float* bond_emb_b  = (const float*)d_in[19];
    const float* bond_upd_w  = (const float*)d_in[20];
    const float* bond_upd_b  = (const float*)d_in[21];

    float* outp     = (float*)d_out;                      // NNODE x 256
    float* bond_out = outp + (size_t)NNODE * 256;         // EB x 256

    float *q, *k, *v, *abvb, *cat, *cat2;
    cudaGetSymbolAddress((void**)&q, d_q);
    cudaGetSymbolAddress((void**)&k, d_k);
    cudaGetSymbolAddress((void**)&v, d_v);
    cudaGetSymbolAddress((void**)&abvb, d_abvb);
    cudaGetSymbolAddress((void**)&cat, d_cat);
    cudaGetSymbolAddress((void**)&cat2, d_cat2);

    const int* src = bond_idx;        // bond_idx[0]
    const int* dst = bond_idx + EL;   // bond_idx[1]

    init_kernel<<<(NNODE * 512 + 255) / 256, 256>>>();

    dim3 gQKV(512 / 128, (NNODE + 127) / 128);
    sgemm128<<<gQKV, 256>>>(f_node, Wq_w, Wq_b, q, NNODE, 256, 512);
    sgemm128<<<gQKV, 256>>>(f_node, Wk_w, Wk_b, k, NNODE, 256, 512);
    sgemm128<<<gQKV, 256>>>(f_node, Wv_w, Wv_b, v, NNODE, 256, 512);
    sgemm128<<<dim3(512 / 128, (EB + 127) / 128), 256>>>(f_bond, bond_emb_w, bond_emb_b,
                                                         abvb, EB, 256, 512);

    kg_kernel<<<(NNODE * 256 + 255) / 256, 256>>>(deg, deg_emb);
    absum_kernel<<<(EB + 7) / 8, 256>>>();
    dsum_kernel<<<3, 256>>>(dist_emb);

    lscore_kernel<<<(EL + 7) / 8, 256>>>(src, dst);
    gscore_kernel<<<(EG + 7) / 8, 256>>>(qidx, kidx, dist);
    gbond_kernel<<<(EB * 8 + 255) / 256, 256>>>(abi);
    gmax_kernel<<<(EG * 8 + 255) / 256, 256>>>(qidx);

    laccum_kernel<<<(EL + 7) / 8, 256>>>(src, dst);
    gaccum_kernel<<<(EG + 7) / 8, 256>>>(qidx, kidx);
    norm_kernel<<<(NNODE * 512 + 255) / 256, 256>>>();

    sgemm128<<<dim3(256 / 128, (NNODE + 127) / 128), 256>>>(cat, out_w, out_b,
                                                            outp, NNODE, 512, 256);
    cat2_kernel<<<(EB * 512 + 255) / 256, 256>>>(f_bond, src, outp);
    sgemm128<<<dim3(256 / 128, (EB + 127) / 128), 256>>>(cat2, bond_upd_w, bond_upd_b,
                                                         bond_out, EB, 512, 256);
}

// round 7
// speedup vs baseline: 1.5390x; 1.5390x over previous
#include <cuda_runtime.h>
#include <cuda_bf16.h>
#include <math.h>
#include <stdint.h>

#define NNODE 20000
#define EL 80000
#define EB 60000
#define EG 400000
#define SCALE 0.17677669529663687f   // 1/sqrt(32)

// ---------------- scratch (static device globals: allowed) ----------------
__device__ float d_qkv[NNODE * 1536];   // [q_loc | q_glob | k_loc | k_glob | v_loc | v_glob]
__device__ float d_kg[NNODE * 256];
__device__ float d_abvb[EB * 512];
__device__ float d_absum[EB * 8];
__device__ float d_dsum[65 * 8];
__device__ float d_sloc[EL * 8];
__device__ float d_sg[EG * 8];
__device__ float d_mloc[NNODE * 8];
__device__ float d_dloc[NNODE * 8];
__device__ float d_mg[NNODE * 8];
__device__ float d_dg[NNODE * 8];
__device__ float d_cat[NNODE * 512];
__device__ float d_cat2[EB * 512];
__device__ float d_bias3[1536];
// bf16 split buffers
__device__ __nv_bfloat16 d_ah[60000 * 512];
__device__ __nv_bfloat16 d_al[60000 * 512];
__device__ __nv_bfloat16 d_bh[1536 * 256];
__device__ __nv_bfloat16 d_bl[1536 * 256];

// ---------------- helpers ----------------
__device__ __forceinline__ void atomicMaxF(float* a, float v) {
    if (v >= 0.f) atomicMax((int*)a, __float_as_int(v));
    else          atomicMin((unsigned int*)a, __float_as_uint(v));
}
__device__ __forceinline__ void redAdd4(float* p, float x, float y, float z, float w) {
    asm volatile("red.global.add.v4.f32 [%0], {%1,%2,%3,%4};"
                 :: "l"(p), "f"(x), "f"(y), "f"(z), "f"(w) : "memory");
}
__device__ __forceinline__ uint32_t smem_u32(const void* p) {
    uint32_t a;
    asm("{ .reg .u64 t; cvta.to.shared.u64 t, %1; cvt.u32.u64 %0, t; }" : "=r"(a) : "l"(p));
    return a;
}
#define SWZ(x) ((x) ^ (((x) >> 3) & 0x70))

#define LDSM4(r0, r1, r2, r3, a) \
    asm volatile("ldmatrix.sync.aligned.m8n8.x4.shared.b16 {%0,%1,%2,%3}, [%4];" \
                 : "=r"(r0), "=r"(r1), "=r"(r2), "=r"(r3) : "r"(a))

#define MMA16816(c, a, b) \
    asm volatile("mma.sync.aligned.m16n8k16.row.col.f32.bf16.bf16.f32 " \
                 "{%0,%1,%2,%3}, {%4,%5,%6,%7}, {%8,%9}, {%0,%1,%2,%3};" \
                 : "+f"((c)[0]), "+f"((c)[1]), "+f"((c)[2]), "+f"((c)[3]) \
                 : "r"((a)[0]), "r"((a)[1]), "r"((a)[2]), "r"((a)[3]), \
                   "r"((b)[0]), "r"((b)[1]))

// SMEM layout for gemm_mma (four 128x64 bf16 tiles, SW128-swizzled)
#define G_AH   0
#define G_AL   16384
#define G_BH   32768
#define G_BL   49152
#define G_SMEM 65536

// ---------------- mma.sync GEMM: C[M,N] = (Ah+Al)[M,K] @ (Bh+Bl)[N,K]^T + bias ----------------
// grid (N/128, ceil(M/128)), 256 threads. K % 64 == 0, N % 128 == 0.
__global__ void __launch_bounds__(256, 2) gemm_mma(
    const __nv_bfloat16* __restrict__ Ah, const __nv_bfloat16* __restrict__ Al,
    const __nv_bfloat16* __restrict__ Bh, const __nv_bfloat16* __restrict__ Bl,
    const float* __restrict__ bias, float* __restrict__ C,
    int M, int K, int N)
{
    extern __shared__ char smem[];
    const uint32_t sb = smem_u32(smem);
    const int tid = threadIdx.x, wid = tid >> 5, lane = tid & 31;
    const int bm = blockIdx.y << 7, bn = blockIdx.x << 7;

    const int warp_m = wid & 3, warp_n = wid >> 2;
    const int m0 = warp_m * 32, n0 = warp_n * 64;

    float acc[2][8][4];
#pragma unroll
    for (int i = 0; i < 2; i++)
#pragma unroll
        for (int j = 0; j < 8; j++)
#pragma unroll
            for (int l = 0; l < 4; l++) acc[i][j][l] = 0.f;

    // ldmatrix per-lane base offsets (row part)
    const int lrow = lane & 15;                 // row within 16-row block
    const int lcb  = (lane & 16) ? 16 : 0;      // +16B for k8..15 tiles

    const int nkt = K >> 6;
    const int r0 = tid >> 3;      // 0..31  (load row within 32-row piece)
    const int cc = tid & 7;       // 16B chunk within 128B row

    for (int kt = 0; kt < nkt; kt++) {
        const int kofs = kt * 64 + cc * 8;   // bf16 elems
#pragma unroll
        for (int i = 0; i < 16; i++) {
            const int piece = i >> 2;       // 0:Ah 1:Al 2:Bh 3:Bl
            const int r = (i & 3) * 32 + r0;
            const __nv_bfloat16* g;
            uint32_t base;
            unsigned sz = 16;
            if (piece == 0)      { int row = bm + r; if (row >= M) { row = 0; sz = 0; } g = Ah + (size_t)row * K; base = G_AH; }
            else if (piece == 1) { int row = bm + r; if (row >= M) { row = 0; sz = 0; } g = Al + (size_t)row * K; base = G_AL; }
            else if (piece == 2) { g = Bh + (size_t)(bn + r) * K; base = G_BH; }
            else                 { g = Bl + (size_t)(bn + r) * K; base = G_BL; }
            g += kofs;
            uint32_t dst = sb + base + SWZ(r * 128 + cc * 16);
            asm volatile("cp.async.cg.shared.global [%0], [%1], 16, %2;"
                         :: "r"(dst), "l"(g), "r"(sz));
        }
        asm volatile("cp.async.commit_group;");
        asm volatile("cp.async.wait_group 0;");
        __syncthreads();

#pragma unroll
        for (int s = 0; s < 3; s++) {
            const uint32_t abase = sb + ((s == 1) ? G_AL : G_AH);
            const uint32_t bbase = sb + ((s == 2) ? G_BL : G_BH);
#pragma unroll
            for (int k16 = 0; k16 < 4; k16++) {
                const int cb = k16 * 32 + lcb;
                uint32_t a[2][4];
#pragma unroll
                for (int mt = 0; mt < 2; mt++) {
                    uint32_t ad = abase + SWZ((m0 + mt * 16 + lrow) * 128 + cb);
                    LDSM4(a[mt][0], a[mt][1], a[mt][2], a[mt][3], ad);
                }
                uint32_t b[8][2];
#pragma unroll
                for (int nt2 = 0; nt2 < 4; nt2++) {
                    uint32_t bd = bbase + SWZ((n0 + nt2 * 16 + lrow) * 128 + cb);
                    uint32_t t0, t1, t2, t3;
                    LDSM4(t0, t1, t2, t3, bd);
                    b[nt2 * 2 + 0][0] = t0; b[nt2 * 2 + 0][1] = t2;
                    b[nt2 * 2 + 1][0] = t1; b[nt2 * 2 + 1][1] = t3;
                }
#pragma unroll
                for (int mt = 0; mt < 2; mt++)
#pragma unroll
                    for (int nt = 0; nt < 8; nt++)
                        MMA16816(acc[mt][nt], a[mt], b[nt]);
            }
        }
        __syncthreads();
    }

    // epilogue: acc[mt][nt] rows m0+mt*16+lane/4 (+8), cols n0+nt*8+(lane%4)*2
    const int er = lane >> 2, ec = (lane & 3) * 2;
#pragma unroll
    for (int mt = 0; mt < 2; mt++) {
#pragma unroll
        for (int half = 0; half < 2; half++) {
            int row = bm + m0 + mt * 16 + er + half * 8;
            if (row < M) {
                float* crow = C + (size_t)row * N;
#pragma unroll
                for (int nt = 0; nt < 8; nt++) {
                    int col = bn + n0 + nt * 8 + ec;
                    float2 o;
                    o.x = acc[mt][nt][half * 2 + 0] + bias[col];
                    o.y = acc[mt][nt][half * 2 + 1] + bias[col + 1];
                    *(float2*)(crow + col) = o;
                }
            }
        }
    }
}

// ---------------- split kernels ----------------
__global__ void splitA_kernel(const float* __restrict__ A,
                              __nv_bfloat16* __restrict__ hi, __nv_bfloat16* __restrict__ lo,
                              int n) {
    int t = blockIdx.x * blockDim.x + threadIdx.x;
    if (t >= n) return;
    float a = A[t];
    __nv_bfloat16 h = __float2bfloat16(a);
    hi[t] = h;
    lo[t] = __float2bfloat16(a - __bfloat162float(h));
}

// B [K,N] fp32 -> Bt hi/lo rows [rowOff + n][k] bf16 (transposed)
__global__ void splitBT_kernel(const float* __restrict__ B,
                               __nv_bfloat16* __restrict__ hi, __nv_bfloat16* __restrict__ lo,
                               int K, int N, int rowOff) {
    int t = blockIdx.x * blockDim.x + threadIdx.x;
    if (t >= K * N) return;
    int k = t / N, n = t % N;
    float a = B[t];
    __nv_bfloat16 h = __float2bfloat16(a);
    size_t idx = (size_t)(rowOff + n) * K + k;
    hi[idx] = h;
    lo[idx] = __float2bfloat16(a - __bfloat162float(h));
}

__global__ void biaspack_kernel(const float* __restrict__ b0, const float* __restrict__ b1,
                                const float* __restrict__ b2) {
    int t = blockIdx.x * blockDim.x + threadIdx.x;
    if (t >= 1536) return;
    d_bias3[t] = (t < 512) ? b0[t] : (t < 1024) ? b1[t - 512] : b2[t - 1024];
}

// ---------------- small kernels ----------------
__global__ void init_kernel() {
    int t = blockIdx.x * blockDim.x + threadIdx.x;
    if (t < NNODE * 512) d_cat[t] = 0.f;
    if (t < NNODE * 8) {
        d_dloc[t] = 0.f;
        d_dg[t] = 0.f;
        d_mloc[t] = __int_as_float(0xff800000);
        d_mg[t] = __int_as_float(0xff800000);
    }
}

__global__ void kg_kernel(const int* __restrict__ deg, const float* __restrict__ deg_emb) {
    int t = blockIdx.x * blockDim.x + threadIdx.x;
    if (t >= NNODE * 256) return;
    int n = t >> 8, c = t & 255;
    d_kg[t] = d_qkv[(size_t)n * 1536 + 768 + c] + deg_emb[(size_t)deg[n] * 256 + c];
}

__global__ void absum_kernel() {
    int e = blockIdx.x * (blockDim.x >> 5) + (threadIdx.x >> 5);
    if (e >= EB) return;
    int lane = threadIdx.x & 31;
    const float4* p = (const float4*)(d_abvb + (size_t)e * 512) + lane * 2;
    float4 a = p[0], b = p[1];
    float s = a.x + a.y + a.z + a.w + b.x + b.y + b.z + b.w;
    s += __shfl_xor_sync(0xffffffffu, s, 1);
    s += __shfl_xor_sync(0xffffffffu, s, 2);
    if ((lane & 3) == 0) d_absum[e * 8 + (lane >> 2)] = s;
}

__global__ void dsum_kernel(const float* __restrict__ dist_emb) {
    int t = blockIdx.x * blockDim.x + threadIdx.x;
    if (t >= 65 * 8) return;
    int r = t >> 3, h = t & 7;
    const float* p = dist_emb + (size_t)r * 256 + h * 32;
    float s = 0.f;
#pragma unroll
    for (int d = 0; d < 32; d++) s += p[d];
    d_dsum[t] = s;
}

__global__ void lscore_kernel(const int* __restrict__ src_arr, const int* __restrict__ dst_arr) {
    int e = blockIdx.x * (blockDim.x >> 5) + (threadIdx.x >> 5);
    if (e >= EL) return;
    int lane = threadIdx.x & 31;
    int src = src_arr[e], dst = dst_arr[e];
    const float4* qp = (const float4*)(d_qkv + (size_t)dst * 1536) + lane * 2;
    const float4* kp = (const float4*)(d_qkv + (size_t)src * 1536 + 512) + lane * 2;
    float4 a0 = qp[0], a1 = qp[1], b0 = kp[0], b1 = kp[1];
    float s = a0.x * b0.x + a0.y * b0.y + a0.z * b0.z + a0.w * b0.w
            + a1.x * b1.x + a1.y * b1.y + a1.z * b1.z + a1.w * b1.w;
    s += __shfl_xor_sync(0xffffffffu, s, 1);
    s += __shfl_xor_sync(0xffffffffu, s, 2);
    if ((lane & 3) == 0) {
        int h = lane >> 2;
        if (e < EB) s += d_absum[e * 8 + h];
        s *= SCALE;
        d_sloc[e * 8 + h] = s;
        atomicMaxF(&d_mloc[dst * 8 + h], s);
    }
}

__global__ void gscore_kernel(const int* __restrict__ qi, const int* __restrict__ ki,
                              const int* __restrict__ dist) {
    int e = blockIdx.x * (blockDim.x >> 5) + (threadIdx.x >> 5);
    if (e >= EG) return;
    int lane = threadIdx.x & 31;
    int a = qi[e], b = ki[e], dd = dist[e];
    const float4* qp = (const float4*)(d_qkv + (size_t)a * 1536 + 256) + lane * 2;
    const float4* kp = (const float4*)(d_kg + (size_t)b * 256) + lane * 2;
    float4 a0 = qp[0], a1 = qp[1], b0 = kp[0], b1 = kp[1];
    float s = a0.x * b0.x + a0.y * b0.y + a0.z * b0.z + a0.w * b0.w
            + a1.x * b1.x + a1.y * b1.y + a1.z * b1.z + a1.w * b1.w;
    s += __shfl_xor_sync(0xffffffffu, s, 1);
    s += __shfl_xor_sync(0xffffffffu, s, 2);
    if ((lane & 3) == 0) {
        int h = lane >> 2;
        d_sg[(size_t)e * 8 + h] = (s + d_dsum[dd * 8 + h]) * SCALE;
    }
}

__global__ void gbond_kernel(const int* __restrict__ abi) {
    int t = blockIdx.x * blockDim.x + threadIdx.x;
    if (t >= EB * 8) return;
    int j = t >> 3, h = t & 7;
    int e = abi[j];
    d_sg[(size_t)e * 8 + h] += d_absum[t] * SCALE;
}

__global__ void gmax_kernel(const int* __restrict__ qi) {
    int t = blockIdx.x * blockDim.x + threadIdx.x;
    if (t >= EG * 8) return;
    int e = t >> 3, h = t & 7;
    atomicMaxF(&d_mg[(size_t)qi[e] * 8 + h], d_sg[t]);
}

__global__ void laccum_kernel(const int* __restrict__ src_arr, const int* __restrict__ dst_arr) {
    int e = blockIdx.x * (blockDim.x >> 5) + (threadIdx.x >> 5);
    if (e >= EL) return;
    int lane = threadIdx.x & 31;
    int h = lane >> 2;
    int src = src_arr[e], dst = dst_arr[e];
    float w = __expf(d_sloc[e * 8 + h] - d_mloc[dst * 8 + h]);
    if ((lane & 3) == 0) atomicAdd(&d_dloc[dst * 8 + h], w);
    const float4* vp = (const float4*)(d_qkv + (size_t)src * 1536 + 1024) + lane * 2;
    float4 v0 = vp[0], v1 = vp[1];
    if (e < EB) {
        const float4* bp = (const float4*)(d_abvb + (size_t)e * 512 + 256) + lane * 2;
        float4 c0 = bp[0], c1 = bp[1];
        v0.x += c0.x; v0.y += c0.y; v0.z += c0.z; v0.w += c0.w;
        v1.x += c1.x; v1.y += c1.y; v1.z += c1.z; v1.w += c1.w;
    }
    float* outp = d_cat + (size_t)dst * 512 + lane * 8;
    redAdd4(outp,     w * v0.x, w * v0.y, w * v0.z, w * v0.w);
    redAdd4(outp + 4, w * v1.x, w * v1.y, w * v1.z, w * v1.w);
}

__global__ void gaccum_kernel(const int* __restrict__ qi, const int* __restrict__ ki) {
    int e = blockIdx.x * (blockDim.x >> 5) + (threadIdx.x >> 5);
    if (e >= EG) return;
    int lane = threadIdx.x & 31;
    int h = lane >> 2;
    int a = qi[e], b = ki[e];
    float w = __expf(d_sg[(size_t)e * 8 + h] - d_mg[(size_t)a * 8 + h]);
    if ((lane & 3) == 0) atomicAdd(&d_dg[(size_t)a * 8 + h], w);
    const float4* vp = (const float4*)(d_qkv + (size_t)b * 1536 + 1280) + lane * 2;
    float4 v0 = vp[0], v1 = vp[1];
    float* outp = d_cat + (size_t)a * 512 + 256 + lane * 8;
    redAdd4(outp,     w * v0.x, w * v0.y, w * v0.z, w * v0.w);
    redAdd4(outp + 4, w * v1.x, w * v1.y, w * v1.z, w * v1.w);
}

__global__ void norm_kernel() {
    int t = blockIdx.x * blockDim.x + threadIdx.x;
    if (t >= NNODE * 512) return;
    int n = t >> 9, c = t & 511;
    float d = (c < 256) ? d_dloc[n * 8 + (c >> 5)] : d_dg[n * 8 + ((c - 256) >> 5)];
    float num = d_cat[t];
    d_cat[t] = (d > 0.f) ? num / d : 0.f;
}

__global__ void cat2_kernel(const float* __restrict__ f_bond, const int* __restrict__ src_arr,
                            const float* __restrict__ outp) {
    int t = blockIdx.x * blockDim.x + threadIdx.x;
    if (t >= EB * 512) return;
    int e = t >> 9, c = t & 511;
    d_cat2[t] = (c < 256) ? f_bond[(size_t)e * 256 + c]
                          : outp[(size_t)src_arr[e] * 256 + (c - 256)];
}

// ---------------- launch ----------------
extern "C" void kernel_launch(void* const* d_in, const int* in_sizes, int n_in,
                              void* d_out, int out_size) {
    const float* f_node      = (const float*)d_in[0];
    const float* f_bond      = (const float*)d_in[1];
    const int*   deg         = (const int*)d_in[2];
    const int*   dist        = (const int*)d_in[3];
    const int*   bond_idx    = (const int*)d_in[4];
    const int*   qidx        = (const int*)d_in[5];
    const int*   kidx        = (const int*)d_in[6];
    const int*   abi         = (const int*)d_in[7];
    const float* deg_emb     = (const float*)d_in[8];
    const float* dist_emb    = (const float*)d_in[9];
    const float* Wq_w        = (const float*)d_in[10];
    const float* Wq_b        = (const float*)d_in[11];
    const float* Wk_w        = (const float*)d_in[12];
    const float* Wk_b        = (const float*)d_in[13];
    const float* Wv_w        = (const float*)d_in[14];
    const float* Wv_b        = (const float*)d_in[15];
    const float* out_w       = (const float*)d_in[16];
    const float* out_b       = (const float*)d_in[17];
    const float* bond_emb_w  = (const float*)d_in[18];
    const float* bond_emb_b  = (const float*)d_in[19];
    const float* bond_upd_w  = (const float*)d_in[20];
    const float* bond_upd_b  = (const float*)d_in[21];

    float* outp     = (float*)d_out;
    float* bond_out = outp + (size_t)NNODE * 256;

    float *qkv, *abvb, *cat, *cat2, *bias3;
    __nv_bfloat16 *ah, *al, *bh, *bl;
    cudaGetSymbolAddress((void**)&qkv, d_qkv);
    cudaGetSymbolAddress((void**)&abvb, d_abvb);
    cudaGetSymbolAddress((void**)&cat, d_cat);
    cudaGetSymbolAddress((void**)&cat2, d_cat2);
    cudaGetSymbolAddress((void**)&bias3, d_bias3);
    cudaGetSymbolAddress((void**)&ah, d_ah);
    cudaGetSymbolAddress((void**)&al, d_al);
    cudaGetSymbolAddress((void**)&bh, d_bh);
    cudaGetSymbolAddress((void**)&bl, d_bl);

    cudaFuncSetAttribute(gemm_mma, cudaFuncAttributeMaxDynamicSharedMemorySize, G_SMEM);

    const int* src = bond_idx;
    const int* dst = bond_idx + EL;

    init_kernel<<<(NNODE * 512 + 255) / 256, 256>>>();

    // ---- fused QKV GEMM: N = 1536 ----
    splitA_kernel<<<(NNODE * 256 + 255) / 256, 256>>>(f_node, ah, al, NNODE * 256);
    splitBT_kernel<<<(256 * 512 + 255) / 256, 256>>>(Wq_w, bh, bl, 256, 512, 0);
    splitBT_kernel<<<(256 * 512 + 255) / 256, 256>>>(Wk_w, bh, bl, 256, 512, 512);
    splitBT_kernel<<<(256 * 512 + 255) / 256, 256>>>(Wv_w, bh, bl, 256, 512, 1024);
    biaspack_kernel<<<6, 256>>>(Wq_b, Wk_b, Wv_b);
    gemm_mma<<<dim3(12, 157), 256, G_SMEM>>>(ah, al, bh, bl, bias3, qkv, NNODE, 256, 1536);

    // ---- bond embedding GEMM ----
    splitA_kernel<<<(EB * 256 + 255) / 256, 256>>>(f_bond, ah, al, EB * 256);
    splitBT_kernel<<<(256 * 512 + 255) / 256, 256>>>(bond_emb_w, bh, bl, 256, 512, 0);
    gemm_mma<<<dim3(4, 469), 256, G_SMEM>>>(ah, al, bh, bl, bond_emb_b, abvb, EB, 256, 512);

    // ---- attention (edge) phase ----
    kg_kernel<<<(NNODE * 256 + 255) / 256, 256>>>(deg, deg_emb);
    absum_kernel<<<(EB + 7) / 8, 256>>>();
    dsum_kernel<<<3, 256>>>(dist_emb);

    lscore_kernel<<<(EL + 7) / 8, 256>>>(src, dst);
    gscore_kernel<<<(EG + 7) / 8, 256>>>(qidx, kidx, dist);
    gbond_kernel<<<(EB * 8 + 255) / 256, 256>>>(abi);
    gmax_kernel<<<(EG * 8 + 255) / 256, 256>>>(qidx);

    laccum_kernel<<<(EL + 7) / 8, 256>>>(src, dst);
    gaccum_kernel<<<(EG + 7) / 8, 256>>>(qidx, kidx);
    norm_kernel<<<(NNODE * 512 + 255) / 256, 256>>>();

    // ---- output projection ----
    splitA_kernel<<<(NNODE * 512 + 255) / 256, 256>>>(cat, ah, al, NNODE * 512);
    splitBT_kernel<<<(512 * 256 + 255) / 256, 256>>>(out_w, bh, bl, 512, 256, 0);
    gemm_mma<<<dim3(2, 157), 256, G_SMEM>>>(ah, al, bh, bl, out_b, outp, NNODE, 512, 256);

    // ---- bond update ----
    cat2_kernel<<<(EB * 512 + 255) / 256, 256>>>(f_bond, src, outp);
    splitA_kernel<<<(EB * 512 + 255) / 256, 256>>>(cat2, ah, al, EB * 512);
    splitBT_kernel<<<(512 * 256 + 255) / 256, 256>>>(bond_upd_w, bh, bl, 512, 256, 0);
    gemm_mma<<<dim3(2, 469), 256, G_SMEM>>>(ah, al, bh, bl, bond_upd_b, bond_out, EB, 512, 256);
}

// round 11
// speedup vs baseline: 2.3767x; 1.5443x over previous
#include <cuda_runtime.h>
#include <cuda_fp16.h>
#include <math.h>
#include <stdint.h>

#define NNODE 20000
#define EL 80000
#define EB 60000
#define EG 400000
#define SCALE 0.17677669529663687f   // 1/sqrt(32)

// ---------------- scratch (static device globals: allowed) ----------------
__device__ float d_qkv[NNODE * 1536];   // [q_loc | q_glob | k_loc | k_glob | v_loc | v_glob]
__device__ float d_kg[NNODE * 256];
__device__ float d_abvb[EB * 512];
__device__ float d_absum[EB * 8];
__device__ float d_dsum[65 * 8];
__device__ float d_sloc[EL * 8];
__device__ float d_sg[EG * 8];
__device__ float d_mloc[NNODE * 8];
__device__ float d_dloc[NNODE * 8];
__device__ float d_mg[NNODE * 8];
__device__ float d_dg[NNODE * 8];
__device__ float d_cat[NNODE * 512];    // attention numerators (fp32)
__device__ float d_bias3[1536];
// fp16 GEMM operand buffers
__device__ __half d_ah[60000 * 512];
__device__ __half d_bh[1536 * 256];
__device__ __half d_bl[1536 * 256];

// ---------------- helpers ----------------
__device__ __forceinline__ void atomicMaxF(float* a, float v) {
    if (v >= 0.f) atomicMax((int*)a, __float_as_int(v));
    else          atomicMin((unsigned int*)a, __float_as_uint(v));
}
__device__ __forceinline__ void redAdd4(float* p, float x, float y, float z, float w) {
    asm volatile("red.global.add.v4.f32 [%0], {%1,%2,%3,%4};"
                 :: "l"(p), "f"(x), "f"(y), "f"(z), "f"(w) : "memory");
}
__device__ __forceinline__ uint32_t smem_u32(const void* p) {
    uint32_t a;
    asm("{ .reg .u64 t; cvta.to.shared.u64 t, %1; cvt.u32.u64 %0, t; }" : "=r"(a) : "l"(p));
    return a;
}
#define SWZ(x) ((x) ^ (((x) >> 3) & 0x70))

#define LDSM4(r0, r1, r2, r3, a) \
    asm volatile("ldmatrix.sync.aligned.m8n8.x4.shared.b16 {%0,%1,%2,%3}, [%4];" \
                 : "=r"(r0), "=r"(r1), "=r"(r2), "=r"(r3) : "r"(a))

#define MMA16816(c, a, b) \
    asm volatile("mma.sync.aligned.m16n8k16.row.col.f32.f16.f16.f32 " \
                 "{%0,%1,%2,%3}, {%4,%5,%6,%7}, {%8,%9}, {%0,%1,%2,%3};" \
                 : "+f"((c)[0]), "+f"((c)[1]), "+f"((c)[2]), "+f"((c)[3]) \
                 : "r"((a)[0]), "r"((a)[1]), "r"((a)[2]), "r"((a)[3]), \
                   "r"((b)[0]), "r"((b)[1]))

// SMEM: per stage [Ah 16K][Bh 16K][Bl 16K], 2 stages
#define G_STAGE 49152
#define G_BH    16384
#define G_BL    32768
#define G_SMEM  (2 * G_STAGE)

// ---------------- mma.sync GEMM: C[M,N] = Ah[M,K] @ (Bh+Bl)[N,K]^T + bias ----------------
// grid (N/128, ceil(M/128)), 256 threads. K % 64 == 0, N % 128 == 0.
__global__ void __launch_bounds__(256, 2) gemm_mma(
    const __half* __restrict__ Ah,
    const __half* __restrict__ Bh, const __half* __restrict__ Bl,
    const float* __restrict__ bias, float* __restrict__ C,
    int M, int K, int N)
{
    extern __shared__ char smem[];
    const uint32_t sb = smem_u32(smem);
    const int tid = threadIdx.x, wid = tid >> 5, lane = tid & 31;
    const int bm = blockIdx.y << 7, bn = blockIdx.x << 7;

    const int warp_m = wid & 3, warp_n = wid >> 2;
    const int m0 = warp_m * 32, n0 = warp_n * 64;

    float acc[2][8][4];
#pragma unroll
    for (int i = 0; i < 2; i++)
#pragma unroll
        for (int j = 0; j < 8; j++)
#pragma unroll
            for (int l = 0; l < 4; l++) acc[i][j][l] = 0.f;

    const int lrow = lane & 15;
    const int lcb  = (lane & 16) ? 16 : 0;

    const int nkt = K >> 6;
    const int r0 = tid >> 3;      // 0..31
    const int cc = tid & 7;       // 16B chunk within 128B row

    auto issue = [&](int kt) {
        const uint32_t st = sb + (uint32_t)(kt & 1) * G_STAGE;
        const int kofs = kt * 64 + cc * 8;   // fp16 elems
#pragma unroll
        for (int i = 0; i < 12; i++) {
            const int piece = i >> 2;       // 0:Ah 1:Bh 2:Bl
            const int r = (i & 3) * 32 + r0;
            const __half* g;
            uint32_t base;
            unsigned sz = 16;
            if (piece == 0)      { int row = bm + r; if (row >= M) { row = 0; sz = 0; } g = Ah + (size_t)row * K; base = 0; }
            else if (piece == 1) { g = Bh + (size_t)(bn + r) * K; base = G_BH; }
            else                 { g = Bl + (size_t)(bn + r) * K; base = G_BL; }
            g += kofs;
            uint32_t dst = st + base + SWZ(r * 128 + cc * 16);
            asm volatile("cp.async.cg.shared.global [%0], [%1], 16, %2;"
                         :: "r"(dst), "l"(g), "r"(sz));
        }
        asm volatile("cp.async.commit_group;");
    };

    issue(0);

    for (int kt = 0; kt < nkt; kt++) {
        if (kt + 1 < nkt) {
            issue(kt + 1);
            asm volatile("cp.async.wait_group 1;");
        } else {
            asm volatile("cp.async.wait_group 0;");
        }
        __syncthreads();

        const uint32_t st = sb + (uint32_t)(kt & 1) * G_STAGE;
#pragma unroll
        for (int k16 = 0; k16 < 4; k16++) {
            const int cb = k16 * 32 + lcb;
            uint32_t a[2][4];
#pragma unroll
            for (int mt = 0; mt < 2; mt++) {
                uint32_t ad = st + SWZ((m0 + mt * 16 + lrow) * 128 + cb);
                LDSM4(a[mt][0], a[mt][1], a[mt][2], a[mt][3], ad);
            }
#pragma unroll
            for (int sp = 0; sp < 2; sp++) {
                const uint32_t bbase = st + (sp ? G_BL : G_BH);
                uint32_t b[8][2];
#pragma unroll
                for (int nt2 = 0; nt2 < 4; nt2++) {
                    uint32_t bd = bbase + SWZ((n0 + nt2 * 16 + lrow) * 128 + cb);
                    uint32_t t0, t1, t2, t3;
                    LDSM4(t0, t1, t2, t3, bd);
                    b[nt2 * 2 + 0][0] = t0; b[nt2 * 2 + 0][1] = t2;
                    b[nt2 * 2 + 1][0] = t1; b[nt2 * 2 + 1][1] = t3;
                }
#pragma unroll
                for (int mt = 0; mt < 2; mt++)
#pragma unroll
                    for (int nt = 0; nt < 8; nt++)
                        MMA16816(acc[mt][nt], a[mt], b[nt]);
            }
        }
        __syncthreads();
    }

    const int er = lane >> 2, ec = (lane & 3) * 2;
#pragma unroll
    for (int mt = 0; mt < 2; mt++) {
#pragma unroll
        for (int half = 0; half < 2; half++) {
            int row = bm + m0 + mt * 16 + er + half * 8;
            if (row < M) {
                float* crow = C + (size_t)row * N;
#pragma unroll
                for (int nt = 0; nt < 8; nt++) {
                    int col = bn + n0 + nt * 8 + ec;
                    float2 o;
                    o.x = acc[mt][nt][half * 2 + 0] + bias[col];
                    o.y = acc[mt][nt][half * 2 + 1] + bias[col + 1];
                    *(float2*)(crow + col) = o;
                }
            }
        }
    }
}

// ---------------- split kernels ----------------
__global__ void splitA_kernel(const float* __restrict__ A, __half* __restrict__ hi, int n) {
    int t = blockIdx.x * blockDim.x + threadIdx.x;
    if (t >= n) return;
    hi[t] = __float2half(A[t]);
}

// B [K,N] fp32 -> Bt hi/lo rows [rowOff + n][k] fp16 (transposed)
__global__ void splitBT_kernel(const float* __restrict__ B,
                               __half* __restrict__ hi, __half* __restrict__ lo,
                               int K, int N, int rowOff) {
    int t = blockIdx.x * blockDim.x + threadIdx.x;
    if (t >= K * N) return;
    int k = t / N, n = t % N;
    float a = B[t];
    __half h = __float2half(a);
    size_t idx = (size_t)(rowOff + n) * K + k;
    hi[idx] = h;
    lo[idx] = __float2half(a - __half2float(h));
}

__global__ void biaspack_kernel(const float* __restrict__ b0, const float* __restrict__ b1,
                                const float* __restrict__ b2) {
    int t = blockIdx.x * blockDim.x + threadIdx.x;
    if (t >= 1536) return;
    d_bias3[t] = (t < 512) ? b0[t] : (t < 1024) ? b1[t - 512] : b2[t - 1024];
}

// ---------------- small kernels ----------------
__global__ void init_kernel() {
    int t = blockIdx.x * blockDim.x + threadIdx.x;
    if (t < NNODE * 512) d_cat[t] = 0.f;
    if (t < NNODE * 8) {
        d_dloc[t] = 0.f;
        d_dg[t] = 0.f;
        d_mloc[t] = __int_as_float(0xff800000);
        d_mg[t] = __int_as_float(0xff800000);
    }
}

__global__ void kg_kernel(const int* __restrict__ deg, const float* __restrict__ deg_emb) {
    int t = blockIdx.x * blockDim.x + threadIdx.x;
    if (t >= NNODE * 256) return;
    int n = t >> 8, c = t & 255;
    d_kg[t] = d_qkv[(size_t)n * 1536 + 768 + c] + deg_emb[(size_t)deg[n] * 256 + c];
}

__global__ void absum_kernel() {
    int e = blockIdx.x * (blockDim.x >> 5) + (threadIdx.x >> 5);
    if (e >= EB) return;
    int lane = threadIdx.x & 31;
    const float4* p = (const float4*)(d_abvb + (size_t)e * 512) + lane * 2;
    float4 a = p[0], b = p[1];
    float s = a.x + a.y + a.z + a.w + b.x + b.y + b.z + b.w;
    s += __shfl_xor_sync(0xffffffffu, s, 1);
    s += __shfl_xor_sync(0xffffffffu, s, 2);
    if ((lane & 3) == 0) d_absum[e * 8 + (lane >> 2)] = s;
}

__global__ void dsum_kernel(const float* __restrict__ dist_emb) {
    int t = blockIdx.x * blockDim.x + threadIdx.x;
    if (t >= 65 * 8) return;
    int r = t >> 3, h = t & 7;
    const float* p = dist_emb + (size_t)r * 256 + h * 32;
    float s = 0.f;
#pragma unroll
    for (int d = 0; d < 32; d++) s += p[d];
    d_dsum[t] = s;
}

__global__ void lscore_kernel(const int* __restrict__ src_arr, const int* __restrict__ dst_arr) {
    int e = blockIdx.x * (blockDim.x >> 5) + (threadIdx.x >> 5);
    if (e >= EL) return;
    int lane = threadIdx.x & 31;
    int src = src_arr[e], dst = dst_arr[e];
    const float4* qp = (const float4*)(d_qkv + (size_t)dst * 1536) + lane * 2;
    const float4* kp = (const float4*)(d_qkv + (size_t)src * 1536 + 512) + lane * 2;
    float4 a0 = qp[0], a1 = qp[1], b0 = kp[0], b1 = kp[1];
    float s = a0.x * b0.x + a0.y * b0.y + a0.z * b0.z + a0.w * b0.w
            + a1.x * b1.x + a1.y * b1.y + a1.z * b1.z + a1.w * b1.w;
    s += __shfl_xor_sync(0xffffffffu, s, 1);
    s += __shfl_xor_sync(0xffffffffu, s, 2);
    if ((lane & 3) == 0) {
        int h = lane >> 2;
        if (e < EB) s += d_absum[e * 8 + h];
        s *= SCALE;
        d_sloc[e * 8 + h] = s;
        atomicMaxF(&d_mloc[dst * 8 + h], s);
    }
}

__global__ void gscore_kernel(const int* __restrict__ qi, const int* __restrict__ ki,
                              const int* __restrict__ dist) {
    int e = blockIdx.x * (blockDim.x >> 5) + (threadIdx.x >> 5);
    if (e >= EG) return;
    int lane = threadIdx.x & 31;
    int a = qi[e], b = ki[e], dd = dist[e];
    const float4* qp = (const float4*)(d_qkv + (size_t)a * 1536 + 256) + lane * 2;
    const float4* kp = (const float4*)(d_kg + (size_t)b * 256) + lane * 2;
    float4 a0 = qp[0], a1 = qp[1], b0 = kp[0], b1 = kp[1];
    float s = a0.x * b0.x + a0.y * b0.y + a0.z * b0.z + a0.w * b0.w
            + a1.x * b1.x + a1.y * b1.y + a1.z * b1.z + a1.w * b1.w;
    s += __shfl_xor_sync(0xffffffffu, s, 1);
    s += __shfl_xor_sync(0xffffffffu, s, 2);
    if ((lane & 3) == 0) {
        int h = lane >> 2;
        d_sg[(size_t)e * 8 + h] = (s + d_dsum[dd * 8 + h]) * SCALE;
    }
}

__global__ void gbond_kernel(const int* __restrict__ abi) {
    int t = blockIdx.x * blockDim.x + threadIdx.x;
    if (t >= EB * 8) return;
    int j = t >> 3, h = t & 7;
    int e = abi[j];
    d_sg[(size_t)e * 8 + h] += d_absum[t] * SCALE;
}

__global__ void gmax_kernel(const int* __restrict__ qi) {
    int t = blockIdx.x * blockDim.x + threadIdx.x;
    if (t >= EG * 8) return;
    int e = t >> 3, h = t & 7;
    atomicMaxF(&d_mg[(size_t)qi[e] * 8 + h], d_sg[t]);
}

__global__ void laccum_kernel(const int* __restrict__ src_arr, const int* __restrict__ dst_arr) {
    int e = blockIdx.x * (blockDim.x >> 5) + (threadIdx.x >> 5);
    if (e >= EL) return;
    int lane = threadIdx.x & 31;
    int h = lane >> 2;
    int src = src_arr[e], dst = dst_arr[e];
    float w = __expf(d_sloc[e * 8 + h] - d_mloc[dst * 8 + h]);
    if ((lane & 3) == 0) atomicAdd(&d_dloc[dst * 8 + h], w);
    const float4* vp = (const float4*)(d_qkv + (size_t)src * 1536 + 1024) + lane * 2;
    float4 v0 = vp[0], v1 = vp[1];
    if (e < EB) {
        const float4* bp = (const float4*)(d_abvb + (size_t)e * 512 + 256) + lane * 2;
        float4 c0 = bp[0], c1 = bp[1];
        v0.x += c0.x; v0.y += c0.y; v0.z += c0.z; v0.w += c0.w;
        v1.x += c1.x; v1.y += c1.y; v1.z += c1.z; v1.w += c1.w;
    }
    float* outp = d_cat + (size_t)dst * 512 + lane * 8;
    redAdd4(outp,     w * v0.x, w * v0.y, w * v0.z, w * v0.w);
    redAdd4(outp + 4, w * v1.x, w * v1.y, w * v1.z, w * v1.w);
}

__global__ void gaccum_kernel(const int* __restrict__ qi, const int* __restrict__ ki) {
    int e = blockIdx.x * (blockDim.x >> 5) + (threadIdx.x >> 5);
    if (e >= EG) return;
    int lane = threadIdx.x & 31;
    int h = lane >> 2;
    int a = qi[e], b = ki[e];
    float w = __expf(d_sg[(size_t)e * 8 + h] - d_mg[(size_t)a * 8 + h]);
    if ((lane & 3) == 0) atomicAdd(&d_dg[(size_t)a * 8 + h], w);
    const float4* vp = (const float4*)(d_qkv + (size_t)b * 1536 + 1280) + lane * 2;
    float4 v0 = vp[0], v1 = vp[1];
    float* outp = d_cat + (size_t)a * 512 + 256 + lane * 8;
    redAdd4(outp,     w * v0.x, w * v0.y, w * v0.z, w * v0.w);
    redAdd4(outp + 4, w * v1.x, w * v1.y, w * v1.z, w * v1.w);
}

// normalize numerators and emit fp16 A operand directly
__global__ void normsplit_kernel(__half* __restrict__ ah) {
    int t = blockIdx.x * blockDim.x + threadIdx.x;
    if (t >= NNODE * 512) return;
    int n = t >> 9, c = t & 511;
    float d = (c < 256) ? d_dloc[n * 8 + (c >> 5)] : d_dg[n * 8 + ((c - 256) >> 5)];
    float num = d_cat[t];
    ah[t] = __float2half((d > 0.f) ? num / d : 0.f);
}

// concat [f_bond | out[src]] and emit fp16 A operand directly
__global__ void cat2split_kernel(const float* __restrict__ f_bond, const int* __restrict__ src_arr,
                                 const float* __restrict__ outp, __half* __restrict__ ah) {
    int t = blockIdx.x * blockDim.x + threadIdx.x;
    if (t >= EB * 512) return;
    int e = t >> 9, c = t & 511;
    float v = (c < 256) ? f_bond[(size_t)e * 256 + c]
                        : outp[(size_t)src_arr[e] * 256 + (c - 256)];
    ah[t] = __float2half(v);
}

// ---------------- launch ----------------
extern "C" void kernel_launch(void* const* d_in, const int* in_sizes, int n_in,
                              void* d_out, int out_size) {
    const float* f_node      = (const float*)d_in[0];
    const float* f_bond      = (const float*)d_in[1];
    const int*   deg         = (const int*)d_in[2];
    const int*   dist        = (const int*)d_in[3];
    const int*   bond_idx    = (const int*)d_in[4];
    const int*   qidx        = (const int*)d_in[5];
    const int*   kidx        = (const int*)d_in[6];
    const int*   abi         = (const int*)d_in[7];
    const float* deg_emb     = (const float*)d_in[8];
    const float* dist_emb    = (const float*)d_in[9];
    const float* Wq_w        = (const float*)d_in[10];
    const float* Wq_b        = (const float*)d_in[11];
    const float* Wk_w        = (const float*)d_in[12];
    const float* Wk_b        = (const float*)d_in[13];
    const float* Wv_w        = (const float*)d_in[14];
    const float* Wv_b        = (const float*)d_in[15];
    const float* out_w       = (const float*)d_in[16];
    const float* out_b       = (const float*)d_in[17];
    const float* bond_emb_w  = (const float*)d_in[18];
    const float* bond_emb_b  = (const float*)d_in[19];
    const float* bond_upd_w  = (const float*)d_in[20];
    const float* bond_upd_b  = (const float*)d_in[21];

    float* outp     = (float*)d_out;
    float* bond_out = outp + (size_t)NNODE * 256;

    float *qkv, *abvb, *bias3;
    __half *ah, *bh, *bl;
    cudaGetSymbolAddress((void**)&qkv, d_qkv);
    cudaGetSymbolAddress((void**)&abvb, d_abvb);
    cudaGetSymbolAddress((void**)&bias3, d_bias3);
    cudaGetSymbolAddress((void**)&ah, d_ah);
    cudaGetSymbolAddress((void**)&bh, d_bh);
    cudaGetSymbolAddress((void**)&bl, d_bl);

    cudaFuncSetAttribute(gemm_mma, cudaFuncAttributeMaxDynamicSharedMemorySize, G_SMEM);

    const int* src = bond_idx;
    const int* dst = bond_idx + EL;

    init_kernel<<<(NNODE * 512 + 255) / 256, 256>>>();

    // ---- fused QKV GEMM: N = 1536 ----
    splitA_kernel<<<(NNODE * 256 + 255) / 256, 256>>>(f_node, ah, NNODE * 256);
    splitBT_kernel<<<(256 * 512 + 255) / 256, 256>>>(Wq_w, bh, bl, 256, 512, 0);
    splitBT_kernel<<<(256 * 512 + 255) / 256, 256>>>(Wk_w, bh, bl, 256, 512, 512);
    splitBT_kernel<<<(256 * 512 + 255) / 256, 256>>>(Wv_w, bh, bl, 256, 512, 1024);
    biaspack_kernel<<<6, 256>>>(Wq_b, Wk_b, Wv_b);
    gemm_mma<<<dim3(12, 157), 256, G_SMEM>>>(ah, bh, bl, bias3, qkv, NNODE, 256, 1536);

    // ---- bond embedding GEMM ----
    splitA_kernel<<<(EB * 256 + 255) / 256, 256>>>(f_bond, ah, EB * 256);
    splitBT_kernel<<<(256 * 512 + 255) / 256, 256>>>(bond_emb_w, bh, bl, 256, 512, 0);
    gemm_mma<<<dim3(4, 469), 256, G_SMEM>>>(ah, bh, bl, bond_emb_b, abvb, EB, 256, 512);

    // ---- attention (edge) phase ----
    kg_kernel<<<(NNODE * 256 + 255) / 256, 256>>>(deg, deg_emb);
    absum_kernel<<<(EB + 7) / 8, 256>>>();
    dsum_kernel<<<3, 256>>>(dist_emb);

    lscore_kernel<<<(EL + 7) / 8, 256>>>(src, dst);
    gscore_kernel<<<(EG + 7) / 8, 256>>>(qidx, kidx, dist);
    gbond_kernel<<<(EB * 8 + 255) / 256, 256>>>(abi);
    gmax_kernel<<<(EG * 8 + 255) / 256, 256>>>(qidx);

    laccum_kernel<<<(EL + 7) / 8, 256>>>(src, dst);
    gaccum_kernel<<<(EG + 7) / 8, 256>>>(qidx, kidx);

    // ---- output projection (norm fused into split) ----
    normsplit_kernel<<<(NNODE * 512 + 255) / 256, 256>>>(ah);
    splitBT_kernel<<<(512 * 256 + 255) / 256, 256>>>(out_w, bh, bl, 512, 256, 0);
    gemm_mma<<<dim3(2, 157), 256, G_SMEM>>>(ah, bh, bl, out_b, outp, NNODE, 512, 256);

    // ---- bond update (concat fused into split) ----
    cat2split_kernel<<<(EB * 512 + 255) / 256, 256>>>(f_bond, src, outp, ah);
    splitBT_kernel<<<(512 * 256 + 255) / 256, 256>>>(bond_upd_w, bh, bl, 512, 256, 0);
    gemm_mma<<<dim3(2, 469), 256, G_SMEM>>>(ah, bh, bl, bond_upd_b, bond_out, EB, 512, 256);
}

// round 12
// speedup vs baseline: 2.5897x; 1.0896x over previous
#include <cuda_runtime.h>
#include <cuda_fp16.h>
#include <math.h>
#include <stdint.h>

#define NNODE 20000
#define EL 80000
#define EB 60000
#define EG 400000
#define SCALE 0.17677669529663687f   // 1/sqrt(32)

// ---------------- scratch (static device globals: allowed) ----------------
__device__ float d_qkv[NNODE * 1536];   // [q_loc | q_glob | k_loc | k_glob | v_loc | v_glob]
__device__ float d_kg[NNODE * 256];
__device__ float d_abvb[EB * 512];
__device__ float d_absum[EB * 8];
__device__ float d_dsum[65 * 8];
__device__ float d_gbonus[EG * 8];      // pre-scattered bond bonus (scaled)
__device__ float d_dloc[NNODE * 8];
__device__ float d_dg[NNODE * 8];
__device__ float d_cat[NNODE * 512];    // attention numerators (fp32)
__device__ float d_bias3[1536];
// fp16 GEMM operand buffers
__device__ __half d_ah[60000 * 512];
__device__ __half d_bh[1536 * 256];
__device__ __half d_bl[1536 * 256];

// ---------------- helpers ----------------
__device__ __forceinline__ void redAdd4(float* p, float x, float y, float z, float w) {
    asm volatile("red.global.add.v4.f32 [%0], {%1,%2,%3,%4};"
                 :: "l"(p), "f"(x), "f"(y), "f"(z), "f"(w) : "memory");
}
__device__ __forceinline__ uint32_t smem_u32(const void* p) {
    uint32_t a;
    asm("{ .reg .u64 t; cvta.to.shared.u64 t, %1; cvt.u32.u64 %0, t; }" : "=r"(a) : "l"(p));
    return a;
}
#define SWZ(x) ((x) ^ (((x) >> 3) & 0x70))

#define LDSM4(r0, r1, r2, r3, a) \
    asm volatile("ldmatrix.sync.aligned.m8n8.x4.shared.b16 {%0,%1,%2,%3}, [%4];" \
                 : "=r"(r0), "=r"(r1), "=r"(r2), "=r"(r3) : "r"(a))

#define MMA16816(c, a, b) \
    asm volatile("mma.sync.aligned.m16n8k16.row.col.f32.f16.f16.f32 " \
                 "{%0,%1,%2,%3}, {%4,%5,%6,%7}, {%8,%9}, {%0,%1,%2,%3};" \
                 : "+f"((c)[0]), "+f"((c)[1]), "+f"((c)[2]), "+f"((c)[3]) \
                 : "r"((a)[0]), "r"((a)[1]), "r"((a)[2]), "r"((a)[3]), \
                   "r"((b)[0]), "r"((b)[1]))

// SMEM: per stage [Ah 16K][Bh 16K][Bl 16K], 2 stages
#define G_STAGE 49152
#define G_BH    16384
#define G_BL    32768
#define G_SMEM  (2 * G_STAGE)

// ---------------- mma.sync GEMM: C[M,N] = Ah[M,K] @ (Bh+Bl)[N,K]^T + bias ----------------
__global__ void __launch_bounds__(256, 2) gemm_mma(
    const __half* __restrict__ Ah,
    const __half* __restrict__ Bh, const __half* __restrict__ Bl,
    const float* __restrict__ bias, float* __restrict__ C,
    int M, int K, int N)
{
    extern __shared__ char smem[];
    const uint32_t sb = smem_u32(smem);
    const int tid = threadIdx.x, wid = tid >> 5, lane = tid & 31;
    const int bm = blockIdx.y << 7, bn = blockIdx.x << 7;

    const int warp_m = wid & 3, warp_n = wid >> 2;
    const int m0 = warp_m * 32, n0 = warp_n * 64;

    float acc[2][8][4];
#pragma unroll
    for (int i = 0; i < 2; i++)
#pragma unroll
        for (int j = 0; j < 8; j++)
#pragma unroll
            for (int l = 0; l < 4; l++) acc[i][j][l] = 0.f;

    const int lrow = lane & 15;
    const int lcb  = (lane & 16) ? 16 : 0;

    const int nkt = K >> 6;
    const int r0 = tid >> 3;
    const int cc = tid & 7;

    auto issue = [&](int kt) {
        const uint32_t st = sb + (uint32_t)(kt & 1) * G_STAGE;
        const int kofs = kt * 64 + cc * 8;
#pragma unroll
        for (int i = 0; i < 12; i++) {
            const int piece = i >> 2;
            const int r = (i & 3) * 32 + r0;
            const __half* g;
            uint32_t base;
            unsigned sz = 16;
            if (piece == 0)      { int row = bm + r; if (row >= M) { row = 0; sz = 0; } g = Ah + (size_t)row * K; base = 0; }
            else if (piece == 1) { g = Bh + (size_t)(bn + r) * K; base = G_BH; }
            else                 { g = Bl + (size_t)(bn + r) * K; base = G_BL; }
            g += kofs;
            uint32_t dst = st + base + SWZ(r * 128 + cc * 16);
            asm volatile("cp.async.cg.shared.global [%0], [%1], 16, %2;"
                         :: "r"(dst), "l"(g), "r"(sz));
        }
        asm volatile("cp.async.commit_group;");
    };

    issue(0);

    for (int kt = 0; kt < nkt; kt++) {
        if (kt + 1 < nkt) {
            issue(kt + 1);
            asm volatile("cp.async.wait_group 1;");
        } else {
            asm volatile("cp.async.wait_group 0;");
        }
        __syncthreads();

        const uint32_t st = sb + (uint32_t)(kt & 1) * G_STAGE;
#pragma unroll
        for (int k16 = 0; k16 < 4; k16++) {
            const int cb = k16 * 32 + lcb;
            uint32_t a[2][4];
#pragma unroll
            for (int mt = 0; mt < 2; mt++) {
                uint32_t ad = st + SWZ((m0 + mt * 16 + lrow) * 128 + cb);
                LDSM4(a[mt][0], a[mt][1], a[mt][2], a[mt][3], ad);
            }
#pragma unroll
            for (int sp = 0; sp < 2; sp++) {
                const uint32_t bbase = st + (sp ? G_BL : G_BH);
                uint32_t b[8][2];
#pragma unroll
                for (int nt2 = 0; nt2 < 4; nt2++) {
                    uint32_t bd = bbase + SWZ((n0 + nt2 * 16 + lrow) * 128 + cb);
                    uint32_t t0, t1, t2, t3;
                    LDSM4(t0, t1, t2, t3, bd);
                    b[nt2 * 2 + 0][0] = t0; b[nt2 * 2 + 0][1] = t2;
                    b[nt2 * 2 + 1][0] = t1; b[nt2 * 2 + 1][1] = t3;
                }
#pragma unroll
                for (int mt = 0; mt < 2; mt++)
#pragma unroll
                    for (int nt = 0; nt < 8; nt++)
                        MMA16816(acc[mt][nt], a[mt], b[nt]);
            }
        }
        __syncthreads();
    }

    const int er = lane >> 2, ec = (lane & 3) * 2;
#pragma unroll
    for (int mt = 0; mt < 2; mt++) {
#pragma unroll
        for (int half = 0; half < 2; half++) {
            int row = bm + m0 + mt * 16 + er + half * 8;
            if (row < M) {
                float* crow = C + (size_t)row * N;
#pragma unroll
                for (int nt = 0; nt < 8; nt++) {
                    int col = bn + n0 + nt * 8 + ec;
                    float2 o;
                    o.x = acc[mt][nt][half * 2 + 0] + bias[col];
                    o.y = acc[mt][nt][half * 2 + 1] + bias[col + 1];
                    *(float2*)(crow + col) = o;
                }
            }
        }
    }
}

// ---------------- split kernels ----------------
__global__ void splitA_kernel(const float* __restrict__ A, __half* __restrict__ hi, int n) {
    int t = blockIdx.x * blockDim.x + threadIdx.x;
    if (t >= n) return;
    hi[t] = __float2half(A[t]);
}

// single weight: B [K,N] fp32 -> rows [rowOff+n][k] fp16 hi/lo
__global__ void splitBT_kernel(const float* __restrict__ B,
                               __half* __restrict__ hi, __half* __restrict__ lo,
                               int K, int N, int rowOff) {
    int t = blockIdx.x * blockDim.x + threadIdx.x;
    if (t >= K * N) return;
    int k = t / N, n = t % N;
    float a = B[t];
    __half h = __float2half(a);
    size_t idx = (size_t)(rowOff + n) * K + k;
    hi[idx] = h;
    lo[idx] = __float2half(a - __half2float(h));
}

// fused 3-weight transpose-split for QKV (K=256, N=512 each)
__global__ void splitBT3_kernel(const float* __restrict__ B0, const float* __restrict__ B1,
                                const float* __restrict__ B2,
                                __half* __restrict__ hi, __half* __restrict__ lo) {
    int t = blockIdx.x * blockDim.x + threadIdx.x;
    if (t >= 3 * 256 * 512) return;
    int w = t / (256 * 512), r = t % (256 * 512);
    int k = r / 512, n = r % 512;
    const float* B = (w == 0) ? B0 : (w == 1) ? B1 : B2;
    float a = B[r];
    __half h = __float2half(a);
    size_t idx = (size_t)(w * 512 + n) * 256 + k;
    hi[idx] = h;
    lo[idx] = __float2half(a - __half2float(h));
}

__global__ void biaspack_kernel(const float* __restrict__ b0, const float* __restrict__ b1,
                                const float* __restrict__ b2) {
    int t = blockIdx.x * blockDim.x + threadIdx.x;
    if (t >= 1536) return;
    d_bias3[t] = (t < 512) ? b0[t] : (t < 1024) ? b1[t - 512] : b2[t - 1024];
}

// ---------------- small kernels ----------------
__global__ void init_kernel() {
    int t = blockIdx.x * blockDim.x + threadIdx.x;
    if (t < NNODE * 512) d_cat[t] = 0.f;
    if (t < EG * 8) d_gbonus[t] = 0.f;
    if (t < NNODE * 8) {
        d_dloc[t] = 0.f;
        d_dg[t] = 0.f;
    }
}

__global__ void kg_kernel(const int* __restrict__ deg, const float* __restrict__ deg_emb) {
    int t = blockIdx.x * blockDim.x + threadIdx.x;
    if (t >= NNODE * 256) return;
    int n = t >> 8, c = t & 255;
    d_kg[t] = d_qkv[(size_t)n * 1536 + 768 + c] + deg_emb[(size_t)deg[n] * 256 + c];
}

__global__ void absum_kernel() {
    int e = blockIdx.x * (blockDim.x >> 5) + (threadIdx.x >> 5);
    if (e >= EB) return;
    int lane = threadIdx.x & 31;
    const float4* p = (const float4*)(d_abvb + (size_t)e * 512) + lane * 2;
    float4 a = p[0], b = p[1];
    float s = a.x + a.y + a.z + a.w + b.x + b.y + b.z + b.w;
    s += __shfl_xor_sync(0xffffffffu, s, 1);
    s += __shfl_xor_sync(0xffffffffu, s, 2);
    if ((lane & 3) == 0) d_absum[e * 8 + (lane >> 2)] = s;
}

__global__ void dsum_kernel(const float* __restrict__ dist_emb) {
    int t = blockIdx.x * blockDim.x + threadIdx.x;
    if (t >= 65 * 8) return;
    int r = t >> 3, h = t & 7;
    const float* p = dist_emb + (size_t)r * 256 + h * 32;
    float s = 0.f;
#pragma unroll
    for (int d = 0; d < 32; d++) s += p[d];
    d_dsum[t] = s;
}

// scatter bond bonus (scaled) into per-global-edge array
__global__ void scatter_bonus_kernel(const int* __restrict__ abi) {
    int t = blockIdx.x * blockDim.x + threadIdx.x;
    if (t >= EB * 8) return;
    int j = t >> 3, h = t & 7;
    int e = abi[j];
    atomicAdd(&d_gbonus[(size_t)e * 8 + h], d_absum[t] * SCALE);
}

// ---------------- fused local attention: score + exp + denom + numerator ----------------
__global__ void local_fused_kernel(const int* __restrict__ src_arr, const int* __restrict__ dst_arr) {
    int e = blockIdx.x * (blockDim.x >> 5) + (threadIdx.x >> 5);
    if (e >= EL) return;
    int lane = threadIdx.x & 31;
    int h = lane >> 2;
    int src = src_arr[e], dst = dst_arr[e];
    const float4* qp = (const float4*)(d_qkv + (size_t)dst * 1536) + lane * 2;
    const float4* kp = (const float4*)(d_qkv + (size_t)src * 1536 + 512) + lane * 2;
    float4 a0 = qp[0], a1 = qp[1], b0 = kp[0], b1 = kp[1];
    float s = a0.x * b0.x + a0.y * b0.y + a0.z * b0.z + a0.w * b0.w
            + a1.x * b1.x + a1.y * b1.y + a1.z * b1.z + a1.w * b1.w;
    s += __shfl_xor_sync(0xffffffffu, s, 1);
    s += __shfl_xor_sync(0xffffffffu, s, 2);
    if (e < EB) s += d_absum[e * 8 + h];
    float w = __expf(s * SCALE);
    if ((lane & 3) == 0) atomicAdd(&d_dloc[dst * 8 + h], w);
    const float4* vp = (const float4*)(d_qkv + (size_t)src * 1536 + 1024) + lane * 2;
    float4 v0 = vp[0], v1 = vp[1];
    if (e < EB) {
        const float4* bp = (const float4*)(d_abvb + (size_t)e * 512 + 256) + lane * 2;
        float4 c0 = bp[0], c1 = bp[1];
        v0.x += c0.x; v0.y += c0.y; v0.z += c0.z; v0.w += c0.w;
        v1.x += c1.x; v1.y += c1.y; v1.z += c1.z; v1.w += c1.w;
    }
    float* outp = d_cat + (size_t)dst * 512 + lane * 8;
    redAdd4(outp,     w * v0.x, w * v0.y, w * v0.z, w * v0.w);
    redAdd4(outp + 4, w * v1.x, w * v1.y, w * v1.z, w * v1.w);
}

// ---------------- fused global attention: score + bonus + exp + denom + numerator ----------------
__global__ void global_fused_kernel(const int* __restrict__ qi, const int* __restrict__ ki,
                                    const int* __restrict__ dist) {
    int e = blockIdx.x * (blockDim.x >> 5) + (threadIdx.x >> 5);
    if (e >= EG) return;
    int lane = threadIdx.x & 31;
    int h = lane >> 2;
    int a = qi[e], b = ki[e], dd = dist[e];
    const float4* qp = (const float4*)(d_qkv + (size_t)a * 1536 + 256) + lane * 2;
    const float4* kp = (const float4*)(d_kg + (size_t)b * 256) + lane * 2;
    float4 a0 = qp[0], a1 = qp[1], b0 = kp[0], b1 = kp[1];
    float s = a0.x * b0.x + a0.y * b0.y + a0.z * b0.z + a0.w * b0.w
            + a1.x * b1.x + a1.y * b1.y + a1.z * b1.z + a1.w * b1.w;
    s += __shfl_xor_sync(0xffffffffu, s, 1);
    s += __shfl_xor_sync(0xffffffffu, s, 2);
    float w = __expf((s + d_dsum[dd * 8 + h]) * SCALE + d_gbonus[(size_t)e * 8 + h]);
    if ((lane & 3) == 0) atomicAdd(&d_dg[(size_t)a * 8 + h], w);
    const float4* vp = (const float4*)(d_qkv + (size_t)b * 1536 + 1280) + lane * 2;
    float4 v0 = vp[0], v1 = vp[1];
    float* outp = d_cat + (size_t)a * 512 + 256 + lane * 8;
    redAdd4(outp,     w * v0.x, w * v0.y, w * v0.z, w * v0.w);
    redAdd4(outp + 4, w * v1.x, w * v1.y, w * v1.z, w * v1.w);
}

// normalize numerators and emit fp16 A operand directly
__global__ void normsplit_kernel(__half* __restrict__ ah) {
    int t = blockIdx.x * blockDim.x + threadIdx.x;
    if (t >= NNODE * 512) return;
    int n = t >> 9, c = t & 511;
    float d = (c < 256) ? d_dloc[n * 8 + (c >> 5)] : d_dg[n * 8 + ((c - 256) >> 5)];
    float num = d_cat[t];
    ah[t] = __float2half((d > 0.f) ? num / d : 0.f);
}

// concat [f_bond | out[src]] and emit fp16 A operand directly
__global__ void cat2split_kernel(const float* __restrict__ f_bond, const int* __restrict__ src_arr,
                                 const float* __restrict__ outp, __half* __restrict__ ah) {
    int t = blockIdx.x * blockDim.x + threadIdx.x;
    if (t >= EB * 512) return;
    int e = t >> 9, c = t & 511;
    float v = (c < 256) ? f_bond[(size_t)e * 256 + c]
                        : outp[(size_t)src_arr[e] * 256 + (c - 256)];
    ah[t] = __float2half(v);
}

// ---------------- launch ----------------
extern "C" void kernel_launch(void* const* d_in, const int* in_sizes, int n_in,
                              void* d_out, int out_size) {
    const float* f_node      = (const float*)d_in[0];
    const float* f_bond      = (const float*)d_in[1];
    const int*   deg         = (const int*)d_in[2];
    const int*   dist        = (const int*)d_in[3];
    const int*   bond_idx    = (const int*)d_in[4];
    const int*   qidx        = (const int*)d_in[5];
    const int*   kidx        = (const int*)d_in[6];
    const int*   abi         = (const int*)d_in[7];
    const float* deg_emb     = (const float*)d_in[8];
    const float* dist_emb    = (const float*)d_in[9];
    const float* Wq_w        = (const float*)d_in[10];
    const float* Wq_b        = (const float*)d_in[11];
    const float* Wk_w        = (const float*)d_in[12];
    const float* Wk_b        = (const float*)d_in[13];
    const float* Wv_w        = (const float*)d_in[14];
    const float* Wv_b        = (const float*)d_in[15];
    const float* out_w       = (const float*)d_in[16];
    const float* out_b       = (const float*)d_in[17];
    const float* bond_emb_w  = (const float*)d_in[18];
    const float* bond_emb_b  = (const float*)d_in[19];
    const float* bond_upd_w  = (const float*)d_in[20];
    const float* bond_upd_b  = (const float*)d_in[21];

    float* outp     = (float*)d_out;
    float* bond_out = outp + (size_t)NNODE * 256;

    float *qkv, *abvb, *bias3;
    __half *ah, *bh, *bl;
    cudaGetSymbolAddress((void**)&qkv, d_qkv);
    cudaGetSymbolAddress((void**)&abvb, d_abvb);
    cudaGetSymbolAddress((void**)&bias3, d_bias3);
    cudaGetSymbolAddress((void**)&ah, d_ah);
    cudaGetSymbolAddress((void**)&bh, d_bh);
    cudaGetSymbolAddress((void**)&bl, d_bl);

    cudaFuncSetAttribute(gemm_mma, cudaFuncAttributeMaxDynamicSharedMemorySize, G_SMEM);

    const int* src = bond_idx;
    const int* dst = bond_idx + EL;

    init_kernel<<<(NNODE * 512 + 255) / 256, 256>>>();

    // ---- fused QKV GEMM: N = 1536 ----
    splitA_kernel<<<(NNODE * 256 + 255) / 256, 256>>>(f_node, ah, NNODE * 256);
    splitBT3_kernel<<<(3 * 256 * 512 + 255) / 256, 256>>>(Wq_w, Wk_w, Wv_w, bh, bl);
    biaspack_kernel<<<6, 256>>>(Wq_b, Wk_b, Wv_b);
    gemm_mma<<<dim3(12, 157), 256, G_SMEM>>>(ah, bh, bl, bias3, qkv, NNODE, 256, 1536);

    // ---- bond embedding GEMM ----
    splitA_kernel<<<(EB * 256 + 255) / 256, 256>>>(f_bond, ah, EB * 256);
    splitBT_kernel<<<(256 * 512 + 255) / 256, 256>>>(bond_emb_w, bh, bl, 256, 512, 0);
    gemm_mma<<<dim3(4, 469), 256, G_SMEM>>>(ah, bh, bl, bond_emb_b, abvb, EB, 256, 512);

    // ---- attention prep ----
    kg_kernel<<<(NNODE * 256 + 255) / 256, 256>>>(deg, deg_emb);
    absum_kernel<<<(EB + 7) / 8, 256>>>();
    dsum_kernel<<<3, 256>>>(dist_emb);
    scatter_bonus_kernel<<<(EB * 8 + 255) / 256, 256>>>(abi);

    // ---- fused attention passes ----
    local_fused_kernel<<<(EL + 7) / 8, 256>>>(src, dst);
    global_fused_kernel<<<(EG + 7) / 8, 256>>>(qidx, kidx, dist);

    // ---- output projection (norm fused into split) ----
    normsplit_kernel<<<(NNODE * 512 + 255) / 256, 256>>>(ah);
    splitBT_kernel<<<(512 * 256 + 255) / 256, 256>>>(out_w, bh, bl, 512, 256, 0);
    gemm_mma<<<dim3(2, 157), 256, G_SMEM>>>(ah, bh, bl, out_b, outp, NNODE, 512, 256);

    // ---- bond update (concat fused into split) ----
    cat2split_kernel<<<(EB * 512 + 255) / 256, 256>>>(f_bond, src, outp, ah);
    splitBT_kernel<<<(512 * 256 + 255) / 256, 256>>>(bond_upd_w, bh, bl, 512, 256, 0);
    gemm_mma<<<dim3(2, 469), 256, G_SMEM>>>(ah, bh, bl, bond_upd_b, bond_out, EB, 512, 256);
}

// round 14
// speedup vs baseline: 2.7679x; 1.0688x over previous
#include <cuda_runtime.h>
#include <cuda_fp16.h>
#include <math.h>
#include <stdint.h>

#define NNODE 20000
#define EL 80000
#define EB 60000
#define EG 400000
#define SCALE 0.17677669529663687f   // 1/sqrt(32)

// ---------------- scratch (static device globals: allowed) ----------------
__device__ float d_qkv[NNODE * 1536];   // [q_loc | q_glob | k_loc | k_glob | v_loc | v_glob]
__device__ float d_kg[NNODE * 256];
__device__ float d_abvb[EB * 512];
__device__ float d_absum[EB * 8];
__device__ float d_dsum[65 * 8];
__device__ float d_gbonus[EG * 8];      // pre-scattered bond bonus (scaled)
__device__ float d_bias3[1536];
// sort machinery
__device__ int d_lcnt[NNODE + 1];
__device__ int d_gcnt[NNODE + 1];
__device__ int d_lbase[NNODE + 1];
__device__ int d_gbase[NNODE + 1];
__device__ int d_lcur[NNODE];
__device__ int d_gcur[NNODE];
__device__ int d_lperm[EL];
__device__ int d_gperm[EG];
// fp16 GEMM operand buffers
__device__ __half d_ah[60000 * 512];
__device__ __half d_bh[1536 * 256];
__device__ __half d_bl[1536 * 256];

// ---------------- helpers ----------------
__device__ __forceinline__ uint32_t smem_u32(const void* p) {
    uint32_t a;
    asm("{ .reg .u64 t; cvta.to.shared.u64 t, %1; cvt.u32.u64 %0, t; }" : "=r"(a) : "l"(p));
    return a;
}
#define SWZ(x) ((x) ^ (((x) >> 3) & 0x70))

#define LDSM4(r0, r1, r2, r3, a) \
    asm volatile("ldmatrix.sync.aligned.m8n8.x4.shared.b16 {%0,%1,%2,%3}, [%4];" \
                 : "=r"(r0), "=r"(r1), "=r"(r2), "=r"(r3) : "r"(a))

#define MMA16816(c, a, b) \
    asm volatile("mma.sync.aligned.m16n8k16.row.col.f32.f16.f16.f32 " \
                 "{%0,%1,%2,%3}, {%4,%5,%6,%7}, {%8,%9}, {%0,%1,%2,%3};" \
                 : "+f"((c)[0]), "+f"((c)[1]), "+f"((c)[2]), "+f"((c)[3]) \
                 : "r"((a)[0]), "r"((a)[1]), "r"((a)[2]), "r"((a)[3]), \
                   "r"((b)[0]), "r"((b)[1]))

// SMEM: per stage [Ah 16K][Bh 16K][Bl 16K], 2 stages
#define G_STAGE 49152
#define G_BH    16384
#define G_BL    32768
#define G_SMEM  (2 * G_STAGE)

// ---------------- mma.sync GEMM: C[M,N] = Ah[M,K] @ (Bh+Bl)[N,K]^T + bias ----------------
__global__ void __launch_bounds__(256, 2) gemm_mma(
    const __half* __restrict__ Ah,
    const __half* __restrict__ Bh, const __half* __restrict__ Bl,
    const float* __restrict__ bias, float* __restrict__ C,
    int M, int K, int N)
{
    extern __shared__ char smem[];
    const uint32_t sb = smem_u32(smem);
    const int tid = threadIdx.x, wid = tid >> 5, lane = tid & 31;
    const int bm = blockIdx.y << 7, bn = blockIdx.x << 7;

    const int warp_m = wid & 3, warp_n = wid >> 2;
    const int m0 = warp_m * 32, n0 = warp_n * 64;

    float acc[2][8][4];
#pragma unroll
    for (int i = 0; i < 2; i++)
#pragma unroll
        for (int j = 0; j < 8; j++)
#pragma unroll
            for (int l = 0; l < 4; l++) acc[i][j][l] = 0.f;

    const int lrow = lane & 15;
    const int lcb  = (lane & 16) ? 16 : 0;

    const int nkt = K >> 6;
    const int r0 = tid >> 3;
    const int cc = tid & 7;

    auto issue = [&](int kt) {
        const uint32_t st = sb + (uint32_t)(kt & 1) * G_STAGE;
        const int kofs = kt * 64 + cc * 8;
#pragma unroll
        for (int i = 0; i < 12; i++) {
            const int piece = i >> 2;
            const int r = (i & 3) * 32 + r0;
            const __half* g;
            uint32_t base;
            unsigned sz = 16;
            if (piece == 0)      { int row = bm + r; if (row >= M) { row = 0; sz = 0; } g = Ah + (size_t)row * K; base = 0; }
            else if (piece == 1) { g = Bh + (size_t)(bn + r) * K; base = G_BH; }
            else                 { g = Bl + (size_t)(bn + r) * K; base = G_BL; }
            g += kofs;
            uint32_t dst = st + base + SWZ(r * 128 + cc * 16);
            asm volatile("cp.async.cg.shared.global [%0], [%1], 16, %2;"
                         :: "r"(dst), "l"(g), "r"(sz));
        }
        asm volatile("cp.async.commit_group;");
    };

    issue(0);

    for (int kt = 0; kt < nkt; kt++) {
        if (kt + 1 < nkt) {
            issue(kt + 1);
            asm volatile("cp.async.wait_group 1;");
        } else {
            asm volatile("cp.async.wait_group 0;");
        }
        __syncthreads();

        const uint32_t st = sb + (uint32_t)(kt & 1) * G_STAGE;
#pragma unroll
        for (int k16 = 0; k16 < 4; k16++) {
            const int cb = k16 * 32 + lcb;
            uint32_t a[2][4];
#pragma unroll
            for (int mt = 0; mt < 2; mt++) {
                uint32_t ad = st + SWZ((m0 + mt * 16 + lrow) * 128 + cb);
                LDSM4(a[mt][0], a[mt][1], a[mt][2], a[mt][3], ad);
            }
#pragma unroll
            for (int sp = 0; sp < 2; sp++) {
                const uint32_t bbase = st + (sp ? G_BL : G_BH);
                uint32_t b[8][2];
#pragma unroll
                for (int nt2 = 0; nt2 < 4; nt2++) {
                    uint32_t bd = bbase + SWZ((n0 + nt2 * 16 + lrow) * 128 + cb);
                    uint32_t t0, t1, t2, t3;
                    LDSM4(t0, t1, t2, t3, bd);
                    b[nt2 * 2 + 0][0] = t0; b[nt2 * 2 + 0][1] = t2;
                    b[nt2 * 2 + 1][0] = t1; b[nt2 * 2 + 1][1] = t3;
                }
#pragma unroll
                for (int mt = 0; mt < 2; mt++)
#pragma unroll
                    for (int nt = 0; nt < 8; nt++)
                        MMA16816(acc[mt][nt], a[mt], b[nt]);
            }
        }
        __syncthreads();
    }

    const int er = lane >> 2, ec = (lane & 3) * 2;
#pragma unroll
    for (int mt = 0; mt < 2; mt++) {
#pragma unroll
        for (int half = 0; half < 2; half++) {
            int row = bm + m0 + mt * 16 + er + half * 8;
            if (row < M) {
                float* crow = C + (size_t)row * N;
#pragma unroll
                for (int nt = 0; nt < 8; nt++) {
                    int col = bn + n0 + nt * 8 + ec;
                    float2 o;
                    o.x = acc[mt][nt][half * 2 + 0] + bias[col];
                    o.y = acc[mt][nt][half * 2 + 1] + bias[col + 1];
                    *(float2*)(crow + col) = o;
                }
            }
        }
    }
}

// ---------------- split kernels ----------------
__global__ void splitA_kernel(const float* __restrict__ A, __half* __restrict__ hi, int n) {
    int t = blockIdx.x * blockDim.x + threadIdx.x;
    if (t >= n) return;
    hi[t] = __float2half(A[t]);
}

__global__ void splitBT_kernel(const float* __restrict__ B,
                               __half* __restrict__ hi, __half* __restrict__ lo,
                               int K, int N, int rowOff) {
    int t = blockIdx.x * blockDim.x + threadIdx.x;
    if (t >= K * N) return;
    int k = t / N, n = t % N;
    float a = B[t];
    __half h = __float2half(a);
    size_t idx = (size_t)(rowOff + n) * K + k;
    hi[idx] = h;
    lo[idx] = __float2half(a - __half2float(h));
}

__global__ void splitBT3_kernel(const float* __restrict__ B0, const float* __restrict__ B1,
                                const float* __restrict__ B2,
                                __half* __restrict__ hi, __half* __restrict__ lo) {
    int t = blockIdx.x * blockDim.x + threadIdx.x;
    if (t >= 3 * 256 * 512) return;
    int w = t / (256 * 512), r = t % (256 * 512);
    int k = r / 512, n = r % 512;
    const float* B = (w == 0) ? B0 : (w == 1) ? B1 : B2;
    float a = B[r];
    __half h = __float2half(a);
    size_t idx = (size_t)(w * 512 + n) * 256 + k;
    hi[idx] = h;
    lo[idx] = __float2half(a - __half2float(h));
}

__global__ void biaspack_kernel(const float* __restrict__ b0, const float* __restrict__ b1,
                                const float* __restrict__ b2) {
    int t = blockIdx.x * blockDim.x + threadIdx.x;
    if (t >= 1536) return;
    d_bias3[t] = (t < 512) ? b0[t] : (t < 1024) ? b1[t - 512] : b2[t - 1024];
}

// ---------------- init / sort machinery ----------------
__global__ void init_kernel() {
    int t = blockIdx.x * blockDim.x + threadIdx.x;
    if (t < EG * 8) d_gbonus[t] = 0.f;
    if (t <= NNODE) { d_lcnt[t] = 0; d_gcnt[t] = 0; }
}

__global__ void hist_kernel(const int* __restrict__ idx, int* __restrict__ cnt, int n) {
    int t = blockIdx.x * blockDim.x + threadIdx.x;
    if (t < n) atomicAdd(&cnt[idx[t]], 1);
}

// one block per array: blockIdx 0 -> local, 1 -> global. 1024 threads.
__global__ void scan2_kernel() {
    int* cnt  = blockIdx.x ? d_gcnt  : d_lcnt;
    int* base = blockIdx.x ? d_gbase : d_lbase;
    int* cur  = blockIdx.x ? d_gcur  : d_lcur;
    __shared__ int part[1024];
    const int tid = threadIdx.x;
    const int PB = 20;  // bins per thread (20*1024 >= 20000)
    int s = 0;
#pragma unroll 4
    for (int j = 0; j < PB; j++) {
        int b = tid * PB + j;
        if (b < NNODE) s += cnt[b];
    }
    part[tid] = s;
    __syncthreads();
    if (tid == 0) {
        int run = 0;
        for (int i = 0; i < 1024; i++) { int v = part[i]; part[i] = run; run += v; }
    }
    __syncthreads();
    int run = part[tid];
    for (int j = 0; j < PB; j++) {
        int b = tid * PB + j;
        if (b < NNODE) { base[b] = run; cur[b] = run; run += cnt[b]; }
    }
    if (tid == 1023) base[NNODE] = run;
}

__global__ void scatter_kernel(const int* __restrict__ idx, int* __restrict__ cur,
                               int* __restrict__ perm, int n) {
    int t = blockIdx.x * blockDim.x + threadIdx.x;
    if (t < n) {
        int p = atomicAdd(&cur[idx[t]], 1);
        perm[p] = t;
    }
}

// ---------------- small prep kernels ----------------
__global__ void kg_kernel(const int* __restrict__ deg, const float* __restrict__ deg_emb) {
    int t = blockIdx.x * blockDim.x + threadIdx.x;
    if (t >= NNODE * 256) return;
    int n = t >> 8, c = t & 255;
    d_kg[t] = d_qkv[(size_t)n * 1536 + 768 + c] + deg_emb[(size_t)deg[n] * 256 + c];
}

__global__ void absum_kernel() {
    int e = blockIdx.x * (blockDim.x >> 5) + (threadIdx.x >> 5);
    if (e >= EB) return;
    int lane = threadIdx.x & 31;
    const float4* p = (const float4*)(d_abvb + (size_t)e * 512) + lane * 2;
    float4 a = p[0], b = p[1];
    float s = a.x + a.y + a.z + a.w + b.x + b.y + b.z + b.w;
    s += __shfl_xor_sync(0xffffffffu, s, 1);
    s += __shfl_xor_sync(0xffffffffu, s, 2);
    if ((lane & 3) == 0) d_absum[e * 8 + (lane >> 2)] = s;
}

__global__ void dsum_kernel(const float* __restrict__ dist_emb) {
    int t = blockIdx.x * blockDim.x + threadIdx.x;
    if (t >= 65 * 8) return;
    int r = t >> 3, h = t & 7;
    const float* p = dist_emb + (size_t)r * 256 + h * 32;
    float s = 0.f;
#pragma unroll
    for (int d = 0; d < 32; d++) s += p[d];
    d_dsum[t] = s;
}

__global__ void scatter_bonus_kernel(const int* __restrict__ abi) {
    int t = blockIdx.x * blockDim.x + threadIdx.x;
    if (t >= EB * 8) return;
    int j = t >> 3, h = t & 7;
    int e = abi[j];
    atomicAdd(&d_gbonus[(size_t)e * 8 + h], d_absum[t] * SCALE);
}

// ---------------- sorted local attention: warp per node, no atomics ----------------
__global__ void local_sorted_kernel(const int* __restrict__ src_arr, __half* __restrict__ ah) {
    int n = blockIdx.x * (blockDim.x >> 5) + (threadIdx.x >> 5);
    if (n >= NNODE) return;
    int lane = threadIdx.x & 31;
    int h = lane >> 2;

    const float4* qp = (const float4*)(d_qkv + (size_t)n * 1536) + lane * 2;
    float4 q0 = qp[0], q1 = qp[1];

    float acc[8] = {0, 0, 0, 0, 0, 0, 0, 0};
    float dn = 0.f;

    int i0 = d_lbase[n], i1 = d_lbase[n + 1];
    for (int i = i0; i < i1; i++) {
        int e = d_lperm[i];
        int src = src_arr[e];
        const float4* kp = (const float4*)(d_qkv + (size_t)src * 1536 + 512) + lane * 2;
        float4 b0 = kp[0], b1 = kp[1];
        float s = q0.x * b0.x + q0.y * b0.y + q0.z * b0.z + q0.w * b0.w
                + q1.x * b1.x + q1.y * b1.y + q1.z * b1.z + q1.w * b1.w;
        s += __shfl_xor_sync(0xffffffffu, s, 1);
        s += __shfl_xor_sync(0xffffffffu, s, 2);
        if (e < EB) s += d_absum[e * 8 + h];
        float w = __expf(s * SCALE);
        dn += w;
        const float4* vp = (const float4*)(d_qkv + (size_t)src * 1536 + 1024) + lane * 2;
        float4 v0 = vp[0], v1 = vp[1];
        if (e < EB) {
            const float4* bp = (const float4*)(d_abvb + (size_t)e * 512 + 256) + lane * 2;
            float4 c0 = bp[0], c1 = bp[1];
            v0.x += c0.x; v0.y += c0.y; v0.z += c0.z; v0.w += c0.w;
            v1.x += c1.x; v1.y += c1.y; v1.z += c1.z; v1.w += c1.w;
        }
        acc[0] += w * v0.x; acc[1] += w * v0.y; acc[2] += w * v0.z; acc[3] += w * v0.w;
        acc[4] += w * v1.x; acc[5] += w * v1.y; acc[6] += w * v1.z; acc[7] += w * v1.w;
    }
    float inv = (dn > 0.f) ? 1.f / dn : 0.f;
    __half2 p0 = __floats2half2_rn(acc[0] * inv, acc[1] * inv);
    __half2 p1 = __floats2half2_rn(acc[2] * inv, acc[3] * inv);
    __half2 p2 = __floats2half2_rn(acc[4] * inv, acc[5] * inv);
    __half2 p3 = __floats2half2_rn(acc[6] * inv, acc[7] * inv);
    uint4 u = make_uint4(*(uint32_t*)&p0, *(uint32_t*)&p1, *(uint32_t*)&p2, *(uint32_t*)&p3);
    *(uint4*)(ah + (size_t)n * 512 + lane * 8) = u;
}

// ---------------- sorted global attention: warp per node, no atomics ----------------
__global__ void global_sorted_kernel(const int* __restrict__ ki, const int* __restrict__ dist,
                                     __half* __restrict__ ah) {
    int n = blockIdx.x * (blockDim.x >> 5) + (threadIdx.x >> 5);
    if (n >= NNODE) return;
    int lane = threadIdx.x & 31;
    int h = lane >> 2;

    const float4* qp = (const float4*)(d_qkv + (size_t)n * 1536 + 256) + lane * 2;
    float4 q0 = qp[0], q1 = qp[1];

    float acc[8] = {0, 0, 0, 0, 0, 0, 0, 0};
    float dn = 0.f;

    int i0 = d_gbase[n], i1 = d_gbase[n + 1];
    for (int i = i0; i < i1; i++) {
        int e = d_gperm[i];
        int b = ki[e], dd = dist[e];
        const float4* kp = (const float4*)(d_kg + (size_t)b * 256) + lane * 2;
        float4 b0 = kp[0], b1 = kp[1];
        float s = q0.x * b0.x + q0.y * b0.y + q0.z * b0.z + q0.w * b0.w
                + q1.x * b1.x + q1.y * b1.y + q1.z * b1.z + q1.w * b1.w;
        s += __shfl_xor_sync(0xffffffffu, s, 1);
        s += __shfl_xor_sync(0xffffffffu, s, 2);
        float w = __expf((s + d_dsum[dd * 8 + h]) * SCALE + d_gbonus[(size_t)e * 8 + h]);
        dn += w;
        const float4* vp = (const float4*)(d_qkv + (size_t)b * 1536 + 1280) + lane * 2;
        float4 v0 = vp[0], v1 = vp[1];
        acc[0] += w * v0.x; acc[1] += w * v0.y; acc[2] += w * v0.z; acc[3] += w * v0.w;
        acc[4] += w * v1.x; acc[5] += w * v1.y; acc[6] += w * v1.z; acc[7] += w * v1.w;
    }
    float inv = (dn > 0.f) ? 1.f / dn : 0.f;
    __half2 p0 = __floats2half2_rn(acc[0] * inv, acc[1] * inv);
    __half2 p1 = __floats2half2_rn(acc[2] * inv, acc[3] * inv);
    __half2 p2 = __floats2half2_rn(acc[4] * inv, acc[5] * inv);
    __half2 p3 = __floats2half2_rn(acc[6] * inv, acc[7] * inv);
    uint4 u = make_uint4(*(uint32_t*)&p0, *(uint32_t*)&p1, *(uint32_t*)&p2, *(uint32_t*)&p3);
    *(uint4*)(ah + (size_t)n * 512 + 256 + lane * 8) = u;
}

// concat [f_bond | out[src]] and emit fp16 A operand directly
__global__ void cat2split_kernel(const float* __restrict__ f_bond, const int* __restrict__ src_arr,
                                 const float* __restrict__ outp, __half* __restrict__ ah) {
    int t = blockIdx.x * blockDim.x + threadIdx.x;
    if (t >= EB * 512) return;
    int e = t >> 9, c = t & 511;
    float v = (c < 256) ? f_bond[(size_t)e * 256 + c]
                        : outp[(size_t)src_arr[e] * 256 + (c - 256)];
    ah[t] = __float2half(v);
}

// ---------------- launch ----------------
extern "C" void kernel_launch(void* const* d_in, const int* in_sizes, int n_in,
                              void* d_out, int out_size) {
    const float* f_node      = (const float*)d_in[0];
    const float* f_bond      = (const float*)d_in[1];
    const int*   deg         = (const int*)d_in[2];
    const int*   dist        = (const int*)d_in[3];
    const int*   bond_idx    = (const int*)d_in[4];
    const int*   qidx        = (const int*)d_in[5];
    const int*   kidx        = (const int*)d_in[6];
    const int*   abi         = (const int*)d_in[7];
    const float* deg_emb     = (const float*)d_in[8];
    const float* dist_emb    = (const float*)d_in[9];
    const float* Wq_w        = (const float*)d_in[10];
    const float* Wq_b        = (const float*)d_in[11];
    const float* Wk_w        = (const float*)d_in[12];
    const float* Wk_b        = (const float*)d_in[13];
    const float* Wv_w        = (const float*)d_in[14];
    const float* Wv_b        = (const float*)d_in[15];
    const float* out_w       = (const float*)d_in[16];
    const float* out_b       = (const float*)d_in[17];
    const float* bond_emb_w  = (const float*)d_in[18];
    const float* bond_emb_b  = (const float*)d_in[19];
    const float* bond_upd_w  = (const float*)d_in[20];
    const float* bond_upd_b  = (const float*)d_in[21];

    float* outp     = (float*)d_out;
    float* bond_out = outp + (size_t)NNODE * 256;

    float *qkv, *abvb, *bias3;
    __half *ah, *bh, *bl;
    int *lcnt, *gcnt, *lcur, *gcur, *lperm, *gperm;
    cudaGetSymbolAddress((void**)&qkv, d_qkv);
    cudaGetSymbolAddress((void**)&abvb, d_abvb);
    cudaGetSymbolAddress((void**)&bias3, d_bias3);
    cudaGetSymbolAddress((void**)&ah, d_ah);
    cudaGetSymbolAddress((void**)&bh, d_bh);
    cudaGetSymbolAddress((void**)&bl, d_bl);
    cudaGetSymbolAddress((void**)&lcnt, d_lcnt);
    cudaGetSymbolAddress((void**)&gcnt, d_gcnt);
    cudaGetSymbolAddress((void**)&lcur, d_lcur);
    cudaGetSymbolAddress((void**)&gcur, d_gcur);
    cudaGetSymbolAddress((void**)&lperm, d_lperm);
    cudaGetSymbolAddress((void**)&gperm, d_gperm);

    cudaFuncSetAttribute(gemm_mma, cudaFuncAttributeMaxDynamicSharedMemorySize, G_SMEM);

    const int* src = bond_idx;
    const int* dst = bond_idx + EL;

    // ---- init + edge sorts (independent of GEMMs) ----
    init_kernel<<<(EG * 8 + 255) / 256, 256>>>();
    hist_kernel<<<(EL + 255) / 256, 256>>>(dst, lcnt, EL);
    hist_kernel<<<(EG + 255) / 256, 256>>>(qidx, gcnt, EG);
    scan2_kernel<<<2, 1024>>>();
    scatter_kernel<<<(EL + 255) / 256, 256>>>(dst, lcur, lperm, EL);
    scatter_kernel<<<(EG + 255) / 256, 256>>>(qidx, gcur, gperm, EG);

    // ---- fused QKV GEMM: N = 1536 ----
    splitA_kernel<<<(NNODE * 256 + 255) / 256, 256>>>(f_node, ah, NNODE * 256);
    splitBT3_kernel<<<(3 * 256 * 512 + 255) / 256, 256>>>(Wq_w, Wk_w, Wv_w, bh, bl);
    biaspack_kernel<<<6, 256>>>(Wq_b, Wk_b, Wv_b);
    gemm_mma<<<dim3(12, 157), 256, G_SMEM>>>(ah, bh, bl, bias3, qkv, NNODE, 256, 1536);

    // ---- bond embedding GEMM ----
    splitA_kernel<<<(EB * 256 + 255) / 256, 256>>>(f_bond, ah, EB * 256);
    splitBT_kernel<<<(256 * 512 + 255) / 256, 256>>>(bond_emb_w, bh, bl, 256, 512, 0);
    gemm_mma<<<dim3(4, 469), 256, G_SMEM>>>(ah, bh, bl, bond_emb_b, abvb, EB, 256, 512);

    // ---- attention prep ----
    kg_kernel<<<(NNODE * 256 + 255) / 256, 256>>>(deg, deg_emb);
    absum_kernel<<<(EB + 7) / 8, 256>>>();
    dsum_kernel<<<3, 256>>>(dist_emb);
    scatter_bonus_kernel<<<(EB * 8 + 255) / 256, 256>>>(abi);

    // ---- sorted, atomic-free attention (writes fp16 A operand directly) ----
    local_sorted_kernel<<<(NNODE + 7) / 8, 256>>>(src, ah);
    global_sorted_kernel<<<(NNODE + 7) / 8, 256>>>(kidx, dist, ah);

    // ---- output projection ----
    splitBT_kernel<<<(512 * 256 + 255) / 256, 256>>>(out_w, bh, bl, 512, 256, 0);
    gemm_mma<<<dim3(2, 157), 256, G_SMEM>>>(ah, bh, bl, out_b, outp, NNODE, 512, 256);

    // ---- bond update (concat fused into split) ----
    cat2split_kernel<<<(EB * 512 + 255) / 256, 256>>>(f_bond, src, outp, ah);
    splitBT_kernel<<<(512 * 256 + 255) / 256, 256>>>(bond_upd_w, bh, bl, 512, 256, 0);
    gemm_mma<<<dim3(2, 469), 256, G_SMEM>>>(ah, bh, bl, bond_upd_b, bond_out, EB, 512, 256);
}

// round 16
// speedup vs baseline: 2.9925x; 1.0811x over previous
#include <cuda_runtime.h>
#include <cuda_fp16.h>
#include <math.h>
#include <stdint.h>

#define NNODE 20000
#define EL 80000
#define EB 60000
#define EG 400000
#define SCALE 0.17677669529663687f   // 1/sqrt(32)

// ---------------- scratch (static device globals: allowed) ----------------
__device__ float d_qkv[NNODE * 1536];   // [q_loc | q_glob | k_loc | k_glob | v_loc | v_glob]
__device__ float d_kg[NNODE * 256];
__device__ float d_abvb[EB * 512];
__device__ float d_absum[EB * 8];
__device__ float d_dsum[65 * 8];
__device__ float d_gbonus[EG * 8];
__device__ float d_bias3[1536];
// sort machinery
__device__ int d_lcnt[NNODE + 1];
__device__ int d_gcnt[NNODE + 1];
__device__ int d_lbase[NNODE + 1];
__device__ int d_gbase[NNODE + 1];
__device__ int d_lcur[NNODE];
__device__ int d_gcur[NNODE];
__device__ int d_lperm[EL];
__device__ int d_gperm[EG];
// fp16 GEMM operand buffers
__device__ __half d_ah[60000 * 512];     // A for QKV / attention out
__device__ __half d_ah2[60000 * 512];    // A for bond emb / bond update
__device__ __half d_bh[1536 * 256];      // QKV weights hi
__device__ __half d_bl[1536 * 256];      // QKV weights lo
__device__ __half d_bh2[512 * 256];      // bond_emb weights
__device__ __half d_bl2[512 * 256];
__device__ __half d_bho[256 * 512];      // out_w
__device__ __half d_blo[256 * 512];
__device__ __half d_bhu[256 * 512];      // bond_update_w
__device__ __half d_blu[256 * 512];

// ---------------- helpers ----------------
__device__ __forceinline__ uint32_t smem_u32(const void* p) {
    uint32_t a;
    asm("{ .reg .u64 t; cvta.to.shared.u64 t, %1; cvt.u32.u64 %0, t; }" : "=r"(a) : "l"(p));
    return a;
}
#define SWZ(x) ((x) ^ (((x) >> 3) & 0x70))

#define LDSM4(r0, r1, r2, r3, a) \
    asm volatile("ldmatrix.sync.aligned.m8n8.x4.shared.b16 {%0,%1,%2,%3}, [%4];" \
                 : "=r"(r0), "=r"(r1), "=r"(r2), "=r"(r3) : "r"(a))

#define MMA16816(c, a, b) \
    asm volatile("mma.sync.aligned.m16n8k16.row.col.f32.f16.f16.f32 " \
                 "{%0,%1,%2,%3}, {%4,%5,%6,%7}, {%8,%9}, {%0,%1,%2,%3};" \
                 : "+f"((c)[0]), "+f"((c)[1]), "+f"((c)[2]), "+f"((c)[3]) \
                 : "r"((a)[0]), "r"((a)[1]), "r"((a)[2]), "r"((a)[3]), \
                   "r"((b)[0]), "r"((b)[1]))

// SMEM: per stage [Ah 16K][Bh 16K][Bl 16K], 2 stages
#define G_STAGE 49152
#define G_BH    16384
#define G_BL    32768
#define G_SMEM  (2 * G_STAGE)

// ---------------- mma.sync GEMM: C[M,N] = Ah[M,K] @ (Bh+Bl)[N,K]^T + bias ----------------
__global__ void __launch_bounds__(256, 2) gemm_mma(
    const __half* __restrict__ Ah,
    const __half* __restrict__ Bh, const __half* __restrict__ Bl,
    const float* __restrict__ bias, float* __restrict__ C,
    int M, int K, int N)
{
    extern __shared__ char smem[];
    const uint32_t sb = smem_u32(smem);
    const int tid = threadIdx.x, wid = tid >> 5, lane = tid & 31;
    const int bm = blockIdx.y << 7, bn = blockIdx.x << 7;

    const int warp_m = wid & 3, warp_n = wid >> 2;
    const int m0 = warp_m * 32, n0 = warp_n * 64;

    float acc[2][8][4];
#pragma unroll
    for (int i = 0; i < 2; i++)
#pragma unroll
        for (int j = 0; j < 8; j++)
#pragma unroll
            for (int l = 0; l < 4; l++) acc[i][j][l] = 0.f;

    const int lrow = lane & 15;
    const int lcb  = (lane & 16) ? 16 : 0;

    const int nkt = K >> 6;
    const int r0 = tid >> 3;
    const int cc = tid & 7;

    auto issue = [&](int kt) {
        const uint32_t st = sb + (uint32_t)(kt & 1) * G_STAGE;
        const int kofs = kt * 64 + cc * 8;
#pragma unroll
        for (int i = 0; i < 12; i++) {
            const int piece = i >> 2;
            const int r = (i & 3) * 32 + r0;
            const __half* g;
            uint32_t base;
            unsigned sz = 16;
            if (piece == 0)      { int row = bm + r; if (row >= M) { row = 0; sz = 0; } g = Ah + (size_t)row * K; base = 0; }
            else if (piece == 1) { g = Bh + (size_t)(bn + r) * K; base = G_BH; }
            else                 { g = Bl + (size_t)(bn + r) * K; base = G_BL; }
            g += kofs;
            uint32_t dst = st + base + SWZ(r * 128 + cc * 16);
            asm volatile("cp.async.cg.shared.global [%0], [%1], 16, %2;"
                         :: "r"(dst), "l"(g), "r"(sz));
        }
        asm volatile("cp.async.commit_group;");
    };

    issue(0);

    for (int kt = 0; kt < nkt; kt++) {
        if (kt + 1 < nkt) {
            issue(kt + 1);
            asm volatile("cp.async.wait_group 1;");
        } else {
            asm volatile("cp.async.wait_group 0;");
        }
        __syncthreads();

        const uint32_t st = sb + (uint32_t)(kt & 1) * G_STAGE;
#pragma unroll
        for (int k16 = 0; k16 < 4; k16++) {
            const int cb = k16 * 32 + lcb;
            uint32_t a[2][4];
#pragma unroll
            for (int mt = 0; mt < 2; mt++) {
                uint32_t ad = st + SWZ((m0 + mt * 16 + lrow) * 128 + cb);
                LDSM4(a[mt][0], a[mt][1], a[mt][2], a[mt][3], ad);
            }
#pragma unroll
            for (int sp = 0; sp < 2; sp++) {
                const uint32_t bbase = st + (sp ? G_BL : G_BH);
                uint32_t b[8][2];
#pragma unroll
                for (int nt2 = 0; nt2 < 4; nt2++) {
                    uint32_t bd = bbase + SWZ((n0 + nt2 * 16 + lrow) * 128 + cb);
                    uint32_t t0, t1, t2, t3;
                    LDSM4(t0, t1, t2, t3, bd);
                    b[nt2 * 2 + 0][0] = t0; b[nt2 * 2 + 0][1] = t2;
                    b[nt2 * 2 + 1][0] = t1; b[nt2 * 2 + 1][1] = t3;
                }
#pragma unroll
                for (int mt = 0; mt < 2; mt++)
#pragma unroll
                    for (int nt = 0; nt < 8; nt++)
                        MMA16816(acc[mt][nt], a[mt], b[nt]);
            }
        }
        __syncthreads();
    }

    const int er = lane >> 2, ec = (lane & 3) * 2;
#pragma unroll
    for (int mt = 0; mt < 2; mt++) {
#pragma unroll
        for (int half = 0; half < 2; half++) {
            int row = bm + m0 + mt * 16 + er + half * 8;
            if (row < M) {
                float* crow = C + (size_t)row * N;
#pragma unroll
                for (int nt = 0; nt < 8; nt++) {
                    int col = bn + n0 + nt * 8 + ec;
                    float2 o;
                    o.x = acc[mt][nt][half * 2 + 0] + bias[col];
                    o.y = acc[mt][nt][half * 2 + 1] + bias[col + 1];
                    *(float2*)(crow + col) = o;
                }
            }
        }
    }
}

// ---------------- split kernels ----------------
__global__ void splitA_kernel(const float* __restrict__ A, __half* __restrict__ hi, int n) {
    int t = blockIdx.x * blockDim.x + threadIdx.x;
    if (t >= n) return;
    hi[t] = __float2half(A[t]);
}

__global__ void splitBT_kernel(const float* __restrict__ B,
                               __half* __restrict__ hi, __half* __restrict__ lo,
                               int K, int N, int rowOff) {
    int t = blockIdx.x * blockDim.x + threadIdx.x;
    if (t >= K * N) return;
    int k = t / N, n = t % N;
    float a = B[t];
    __half h = __float2half(a);
    size_t idx = (size_t)(rowOff + n) * K + k;
    hi[idx] = h;
    lo[idx] = __float2half(a - __half2float(h));
}

__global__ void splitBT3_kernel(const float* __restrict__ B0, const float* __restrict__ B1,
                                const float* __restrict__ B2,
                                __half* __restrict__ hi, __half* __restrict__ lo) {
    int t = blockIdx.x * blockDim.x + threadIdx.x;
    if (t >= 3 * 256 * 512) return;
    int w = t / (256 * 512), r = t % (256 * 512);
    int k = r / 512, n = r % 512;
    const float* B = (w == 0) ? B0 : (w == 1) ? B1 : B2;
    float a = B[r];
    __half h = __float2half(a);
    size_t idx = (size_t)(w * 512 + n) * 256 + k;
    hi[idx] = h;
    lo[idx] = __float2half(a - __half2float(h));
}

__global__ void biaspack_kernel(const float* __restrict__ b0, const float* __restrict__ b1,
                                const float* __restrict__ b2) {
    int t = blockIdx.x * blockDim.x + threadIdx.x;
    if (t >= 1536) return;
    d_bias3[t] = (t < 512) ? b0[t] : (t < 1024) ? b1[t - 512] : b2[t - 1024];
}

// ---------------- init / sort machinery ----------------
__global__ void init_kernel() {
    int t = blockIdx.x * blockDim.x + threadIdx.x;
    if (t < EG * 8) d_gbonus[t] = 0.f;
    if (t <= NNODE) { d_lcnt[t] = 0; d_gcnt[t] = 0; }
}

__global__ void hist_kernel(const int* __restrict__ idx, int* __restrict__ cnt, int n) {
    int t = blockIdx.x * blockDim.x + threadIdx.x;
    if (t < n) atomicAdd(&cnt[idx[t]], 1);
}

// one block per array: blockIdx 0 -> local, 1 -> global. 1024 threads, shfl scan.
__global__ void scan2_kernel() {
    int* cnt  = blockIdx.x ? d_gcnt  : d_lcnt;
    int* base = blockIdx.x ? d_gbase : d_lbase;
    int* cur  = blockIdx.x ? d_gcur  : d_lcur;
    const int tid = threadIdx.x, lane = tid & 31, wrp = tid >> 5;
    const int PB = 20;
    int c[PB];
    int s = 0;
#pragma unroll
    for (int j = 0; j < PB; j++) {
        int b = tid * PB + j;
        c[j] = (b < NNODE) ? cnt[b] : 0;
        s += c[j];
    }
    // inclusive warp scan of s
    int v = s;
#pragma unroll
    for (int d = 1; d < 32; d <<= 1) {
        int t = __shfl_up_sync(0xffffffffu, v, d);
        if (lane >= d) v += t;
    }
    __shared__ int wsum[32];
    if (lane == 31) wsum[wrp] = v;
    __syncthreads();
    if (wrp == 0) {
        int w = wsum[lane];
#pragma unroll
        for (int d = 1; d < 32; d <<= 1) {
            int t = __shfl_up_sync(0xffffffffu, w, d);
            if (lane >= d) w += t;
        }
        wsum[lane] = w;
    }
    __syncthreads();
    int run = (v - s) + (wrp ? wsum[wrp - 1] : 0);   // exclusive prefix for this thread
#pragma unroll
    for (int j = 0; j < PB; j++) {
        int b = tid * PB + j;
        if (b < NNODE) { base[b] = run; cur[b] = run; run += c[j]; }
    }
    if (tid == 1023) base[NNODE] = run;
}

__global__ void scatter_kernel(const int* __restrict__ idx, int* __restrict__ cur,
                               int* __restrict__ perm, int n) {
    int t = blockIdx.x * blockDim.x + threadIdx.x;
    if (t < n) {
        int p = atomicAdd(&cur[idx[t]], 1);
        perm[p] = t;
    }
}

// ---------------- small prep kernels ----------------
__global__ void kg_kernel(const int* __restrict__ deg, const float* __restrict__ deg_emb) {
    int t = blockIdx.x * blockDim.x + threadIdx.x;
    if (t >= NNODE * 256) return;
    int n = t >> 8, c = t & 255;
    d_kg[t] = d_qkv[(size_t)n * 1536 + 768 + c] + deg_emb[(size_t)deg[n] * 256 + c];
}

__global__ void absum_kernel() {
    int e = blockIdx.x * (blockDim.x >> 5) + (threadIdx.x >> 5);
    if (e >= EB) return;
    int lane = threadIdx.x & 31;
    const float4* p = (const float4*)(d_abvb + (size_t)e * 512) + lane * 2;
    float4 a = p[0], b = p[1];
    float s = a.x + a.y + a.z + a.w + b.x + b.y + b.z + b.w;
    s += __shfl_xor_sync(0xffffffffu, s, 1);
    s += __shfl_xor_sync(0xffffffffu, s, 2);
    if ((lane & 3) == 0) d_absum[e * 8 + (lane >> 2)] = s;
}

__global__ void dsum_kernel(const float* __restrict__ dist_emb) {
    int t = blockIdx.x * blockDim.x + threadIdx.x;
    if (t >= 65 * 8) return;
    int r = t >> 3, h = t & 7;
    const float* p = dist_emb + (size_t)r * 256 + h * 32;
    float s = 0.f;
#pragma unroll
    for (int d = 0; d < 32; d++) s += p[d];
    d_dsum[t] = s;
}

__global__ void scatter_bonus_kernel(const int* __restrict__ abi) {
    int t = blockIdx.x * blockDim.x + threadIdx.x;
    if (t >= EB * 8) return;
    int j = t >> 3, h = t & 7;
    int e = abi[j];
    atomicAdd(&d_gbonus[(size_t)e * 8 + h], d_absum[t] * SCALE);
}

// ---------------- sorted local attention: warp per node, no atomics ----------------
__global__ void local_sorted_kernel(const int* __restrict__ src_arr, __half* __restrict__ ah) {
    int n = blockIdx.x * (blockDim.x >> 5) + (threadIdx.x >> 5);
    if (n >= NNODE) return;
    int lane = threadIdx.x & 31;
    int h = lane >> 2;

    const float4* qp = (const float4*)(d_qkv + (size_t)n * 1536) + lane * 2;
    float4 q0 = qp[0], q1 = qp[1];

    float acc[8] = {0, 0, 0, 0, 0, 0, 0, 0};
    float dn = 0.f;

    int i0 = d_lbase[n], i1 = d_lbase[n + 1];
    for (int i = i0; i < i1; i++) {
        int e = d_lperm[i];
        int src = src_arr[e];
        const float4* kp = (const float4*)(d_qkv + (size_t)src * 1536 + 512) + lane * 2;
        float4 b0 = kp[0], b1 = kp[1];
        float s = q0.x * b0.x + q0.y * b0.y + q0.z * b0.z + q0.w * b0.w
                + q1.x * b1.x + q1.y * b1.y + q1.z * b1.z + q1.w * b1.w;
        s += __shfl_xor_sync(0xffffffffu, s, 1);
        s += __shfl_xor_sync(0xffffffffu, s, 2);
        if (e < EB) s += d_absum[e * 8 + h];
        float w = __expf(s * SCALE);
        dn += w;
        const float4* vp = (const float4*)(d_qkv + (size_t)src * 1536 + 1024) + lane * 2;
        float4 v0 = vp[0], v1 = vp[1];
        if (e < EB) {
            const float4* bp = (const float4*)(d_abvb + (size_t)e * 512 + 256) + lane * 2;
            float4 c0 = bp[0], c1 = bp[1];
            v0.x += c0.x; v0.y += c0.y; v0.z += c0.z; v0.w += c0.w;
            v1.x += c1.x; v1.y += c1.y; v1.z += c1.z; v1.w += c1.w;
        }
        acc[0] += w * v0.x; acc[1] += w * v0.y; acc[2] += w * v0.z; acc[3] += w * v0.w;
        acc[4] += w * v1.x; acc[5] += w * v1.y; acc[6] += w * v1.z; acc[7] += w * v1.w;
    }
    float inv = (dn > 0.f) ? 1.f / dn : 0.f;
    __half2 p0 = __floats2half2_rn(acc[0] * inv, acc[1] * inv);
    __half2 p1 = __floats2half2_rn(acc[2] * inv, acc[3] * inv);
    __half2 p2 = __floats2half2_rn(acc[4] * inv, acc[5] * inv);
    __half2 p3 = __floats2half2_rn(acc[6] * inv, acc[7] * inv);
    uint4 u = make_uint4(*(uint32_t*)&p0, *(uint32_t*)&p1, *(uint32_t*)&p2, *(uint32_t*)&p3);
    *(uint4*)(ah + (size_t)n * 512 + lane * 8) = u;
}

// ---------------- sorted global attention: warp per node, no atomics ----------------
__global__ void global_sorted_kernel(const int* __restrict__ ki, const int* __restrict__ dist,
                                     __half* __restrict__ ah) {
    int n = blockIdx.x * (blockDim.x >> 5) + (threadIdx.x >> 5);
    if (n >= NNODE) return;
    int lane = threadIdx.x & 31;
    int h = lane >> 2;

    const float4* qp = (const float4*)(d_qkv + (size_t)n * 1536 + 256) + lane * 2;
    float4 q0 = qp[0], q1 = qp[1];

    float acc[8] = {0, 0, 0, 0, 0, 0, 0, 0};
    float dn = 0.f;

    int i0 = d_gbase[n], i1 = d_gbase[n + 1];
    for (int i = i0; i < i1; i++) {
        int e = d_gperm[i];
        int b = ki[e], dd = dist[e];
        const float4* kp = (const float4*)(d_kg + (size_t)b * 256) + lane * 2;
        float4 b0 = kp[0], b1 = kp[1];
        float s = q0.x * b0.x + q0.y * b0.y + q0.z * b0.z + q0.w * b0.w
                + q1.x * b1.x + q1.y * b1.y + q1.z * b1.z + q1.w * b1.w;
        s += __shfl_xor_sync(0xffffffffu, s, 1);
        s += __shfl_xor_sync(0xffffffffu, s, 2);
        float w = __expf((s + d_dsum[dd * 8 + h]) * SCALE + d_gbonus[(size_t)e * 8 + h]);
        dn += w;
        const float4* vp = (const float4*)(d_qkv + (size_t)b * 1536 + 1280) + lane * 2;
        float4 v0 = vp[0], v1 = vp[1];
        acc[0] += w * v0.x; acc[1] += w * v0.y; acc[2] += w * v0.z; acc[3] += w * v0.w;
        acc[4] += w * v1.x; acc[5] += w * v1.y; acc[6] += w * v1.z; acc[7] += w * v1.w;
    }
    float inv = (dn > 0.f) ? 1.f / dn : 0.f;
    __half2 p0 = __floats2half2_rn(acc[0] * inv, acc[1] * inv);
    __half2 p1 = __floats2half2_rn(acc[2] * inv, acc[3] * inv);
    __half2 p2 = __floats2half2_rn(acc[4] * inv, acc[5] * inv);
    __half2 p3 = __floats2half2_rn(acc[6] * inv, acc[7] * inv);
    uint4 u = make_uint4(*(uint32_t*)&p0, *(uint32_t*)&p1, *(uint32_t*)&p2, *(uint32_t*)&p3);
    *(uint4*)(ah + (size_t)n * 512 + 256 + lane * 8) = u;
}

__global__ void cat2split_kernel(const float* __restrict__ f_bond, const int* __restrict__ src_arr,
                                 const float* __restrict__ outp, __half* __restrict__ ah) {
    int t = blockIdx.x * blockDim.x + threadIdx.x;
    if (t >= EB * 512) return;
    int e = t >> 9, c = t & 511;
    float v = (c < 256) ? f_bond[(size_t)e * 256 + c]
                        : outp[(size_t)src_arr[e] * 256 + (c - 256)];
    ah[t] = __float2half(v);
}

// ---------------- launch ----------------
extern "C" void kernel_launch(void* const* d_in, const int* in_sizes, int n_in,
                              void* d_out, int out_size) {
    const float* f_node      = (const float*)d_in[0];
    const float* f_bond      = (const float*)d_in[1];
    const int*   deg         = (const int*)d_in[2];
    const int*   dist        = (const int*)d_in[3];
    const int*   bond_idx    = (const int*)d_in[4];
    const int*   qidx        = (const int*)d_in[5];
    const int*   kidx        = (const int*)d_in[6];
    const int*   abi         = (const int*)d_in[7];
    const float* deg_emb     = (const float*)d_in[8];
    const float* dist_emb    = (const float*)d_in[9];
    const float* Wq_w        = (const float*)d_in[10];
    const float* Wq_b        = (const float*)d_in[11];
    const float* Wk_w        = (const float*)d_in[12];
    const float* Wk_b        = (const float*)d_in[13];
    const float* Wv_w        = (const float*)d_in[14];
    const float* Wv_b        = (const float*)d_in[15];
    const float* out_w       = (const float*)d_in[16];
    const float* out_b       = (const float*)d_in[17];
    const float* bond_emb_w  = (const float*)d_in[18];
    const float* bond_emb_b  = (const float*)d_in[19];
    const float* bond_upd_w  = (const float*)d_in[20];
    const float* bond_upd_b  = (const float*)d_in[21];

    float* outp     = (float*)d_out;
    float* bond_out = outp + (size_t)NNODE * 256;

    float *qkv, *abvb, *bias3;
    __half *ah, *ah2, *bh, *bl, *bh2, *bl2, *bho, *blo, *bhu, *blu;
    int *lcnt, *gcnt, *lcur, *gcur, *lperm, *gperm;
    cudaGetSymbolAddress((void**)&qkv, d_qkv);
    cudaGetSymbolAddress((void**)&abvb, d_abvb);
    cudaGetSymbolAddress((void**)&bias3, d_bias3);
    cudaGetSymbolAddress((void**)&ah, d_ah);
    cudaGetSymbolAddress((void**)&ah2, d_ah2);
    cudaGetSymbolAddress((void**)&bh, d_bh);
    cudaGetSymbolAddress((void**)&bl, d_bl);
    cudaGetSymbolAddress((void**)&bh2, d_bh2);
    cudaGetSymbolAddress((void**)&bl2, d_bl2);
    cudaGetSymbolAddress((void**)&bho, d_bho);
    cudaGetSymbolAddress((void**)&blo, d_blo);
    cudaGetSymbolAddress((void**)&bhu, d_bhu);
    cudaGetSymbolAddress((void**)&blu, d_blu);
    cudaGetSymbolAddress((void**)&lcnt, d_lcnt);
    cudaGetSymbolAddress((void**)&gcnt, d_gcnt);
    cudaGetSymbolAddress((void**)&lcur, d_lcur);
    cudaGetSymbolAddress((void**)&gcur, d_gcur);
    cudaGetSymbolAddress((void**)&lperm, d_lperm);
    cudaGetSymbolAddress((void**)&gperm, d_gperm);

    static cudaStream_t s1 = nullptr, s2 = nullptr;
    static cudaEvent_t ev_root = nullptr, ev_sort = nullptr, ev_w = nullptr;
    if (!s1) {
        cudaStreamCreateWithFlags(&s1, cudaStreamNonBlocking);
        cudaStreamCreateWithFlags(&s2, cudaStreamNonBlocking);
        cudaEventCreateWithFlags(&ev_root, cudaEventDisableTiming);
        cudaEventCreateWithFlags(&ev_sort, cudaEventDisableTiming);
        cudaEventCreateWithFlags(&ev_w, cudaEventDisableTiming);
        cudaFuncSetAttribute(gemm_mma, cudaFuncAttributeMaxDynamicSharedMemorySize, G_SMEM);
    }

    const int* src = bond_idx;
    const int* dst = bond_idx + EL;

    // fork
    cudaEventRecord(ev_root, 0);
    cudaStreamWaitEvent(s1, ev_root, 0);
    cudaStreamWaitEvent(s2, ev_root, 0);

    // ---- s1: init + edge sorts ----
    init_kernel<<<(EG * 8 + 255) / 256, 256, 0, s1>>>();
    hist_kernel<<<(EL + 255) / 256, 256, 0, s1>>>(dst, lcnt, EL);
    hist_kernel<<<(EG + 255) / 256, 256, 0, s1>>>(qidx, gcnt, EG);
    scan2_kernel<<<2, 1024, 0, s1>>>();
    scatter_kernel<<<(EL + 255) / 256, 256, 0, s1>>>(dst, lcur, lperm, EL);
    scatter_kernel<<<(EG + 255) / 256, 256, 0, s1>>>(qidx, gcur, gperm, EG);
    cudaEventRecord(ev_sort, s1);

    // ---- s2: input-only splits + dsum ----
    splitA_kernel<<<(EB * 256 + 255) / 256, 256, 0, s2>>>(f_bond, ah2, EB * 256);
    splitBT_kernel<<<(256 * 512 + 255) / 256, 256, 0, s2>>>(bond_emb_w, bh2, bl2, 256, 512, 0);
    splitBT_kernel<<<(512 * 256 + 255) / 256, 256, 0, s2>>>(out_w, bho, blo, 512, 256, 0);
    splitBT_kernel<<<(512 * 256 + 255) / 256, 256, 0, s2>>>(bond_upd_w, bhu, blu, 512, 256, 0);
    dsum_kernel<<<3, 256, 0, s2>>>(dist_emb);
    cudaEventRecord(ev_w, s2);

    // ---- s0: main chain ----
    splitA_kernel<<<(NNODE * 256 + 255) / 256, 256>>>(f_node, ah, NNODE * 256);
    splitBT3_kernel<<<(3 * 256 * 512 + 255) / 256, 256>>>(Wq_w, Wk_w, Wv_w, bh, bl);
    biaspack_kernel<<<6, 256>>>(Wq_b, Wk_b, Wv_b);
    gemm_mma<<<dim3(12, 157), 256, G_SMEM>>>(ah, bh, bl, bias3, qkv, NNODE, 256, 1536);
    kg_kernel<<<(NNODE * 256 + 255) / 256, 256>>>(deg, deg_emb);

    cudaStreamWaitEvent(0, ev_w, 0);
    gemm_mma<<<dim3(4, 469), 256, G_SMEM>>>(ah2, bh2, bl2, bond_emb_b, abvb, EB, 256, 512);
    absum_kernel<<<(EB + 7) / 8, 256>>>();

    cudaStreamWaitEvent(0, ev_sort, 0);
    scatter_bonus_kernel<<<(EB * 8 + 255) / 256, 256>>>(abi);

    local_sorted_kernel<<<(NNODE + 7) / 8, 256>>>(src, ah);
    global_sorted_kernel<<<(NNODE + 7) / 8, 256>>>(kidx, dist, ah);

    gemm_mma<<<dim3(2, 157), 256, G_SMEM>>>(ah, bho, blo, out_b, outp, NNODE, 512, 256);

    cat2split_kernel<<<(EB * 512 + 255) / 256, 256>>>(f_bond, src, outp, ah2);
    gemm_mma<<<dim3(2, 469), 256, G_SMEM>>>(ah2, bhu, blu, bond_upd_b, bond_out, EB, 512, 256);
}